// round 2
// baseline (speedup 1.0000x reference)
#include <cuda_runtime.h>

#define NB 256
#define ND 512
#define NL 64
#define NH 300
#define TM 32

// z transposed scratch: zT[l*NB + b]
__device__ float g_zT[NL * NB];

// ---------------------------------------------------------------------------
// Encoder: one CTA per batch row. Computes h1, h2, z_mean, z_log_var, z.
// Writes z / z_mean / z_log_var to out, and z (transposed) to g_zT scratch.
// ---------------------------------------------------------------------------
__global__ __launch_bounds__(320) void encoder_kernel(
    const float* __restrict__ x, const float* __restrict__ eps,
    const float* __restrict__ enc1_w, const float* __restrict__ enc1_b,
    const float* __restrict__ enc2_w, const float* __restrict__ enc2_b,
    const float* __restrict__ zm_w, const float* __restrict__ zm_b,
    const float* __restrict__ zv_w, const float* __restrict__ zv_b,
    float* __restrict__ out)
{
    __shared__ float xs[ND];
    __shared__ float h1[NH];
    __shared__ float h2[NH];

    const int b = blockIdx.x;
    const int t = threadIdx.x;

    for (int i = t; i < ND; i += blockDim.x) xs[i] = x[b * ND + i];
    __syncthreads();

    if (t < NH) {
        float acc = enc1_b[t];
        const float4* w4 = reinterpret_cast<const float4*>(enc1_w + t * ND);
        const float4* x4 = reinterpret_cast<const float4*>(xs);
        #pragma unroll 4
        for (int k = 0; k < ND / 4; k++) {
            float4 w = w4[k], xv = x4[k];
            acc += w.x * xv.x + w.y * xv.y + w.z * xv.z + w.w * xv.w;
        }
        h1[t] = fmaxf(acc, 0.f);
    }
    __syncthreads();

    if (t < NH) {
        float acc = enc2_b[t];
        const float4* w4 = reinterpret_cast<const float4*>(enc2_w + t * NH);
        const float4* h4 = reinterpret_cast<const float4*>(h1);
        #pragma unroll 4
        for (int k = 0; k < NH / 4; k++) {
            float4 w = w4[k], hv = h4[k];
            acc += w.x * hv.x + w.y * hv.y + w.z * hv.z + w.w * hv.w;
        }
        h2[t] = fmaxf(acc, 0.f);
    }
    __syncthreads();

    if (t < NL) {
        float am = zm_b[t];
        float av = zv_b[t];
        const float4* wm4 = reinterpret_cast<const float4*>(zm_w + t * NH);
        const float4* wv4 = reinterpret_cast<const float4*>(zv_w + t * NH);
        const float4* h4  = reinterpret_cast<const float4*>(h2);
        #pragma unroll 5
        for (int k = 0; k < NH / 4; k++) {
            float4 hv = h4[k];
            float4 wm = wm4[k];
            float4 wv = wv4[k];
            am += wm.x * hv.x + wm.y * hv.y + wm.z * hv.z + wm.w * hv.w;
            av += wv.x * hv.x + wv.y * hv.y + wv.z * hv.z + wv.w * hv.w;
        }
        float e = eps[b * NL + t];
        float z = am + e * expf(0.5f * av);

        g_zT[t * NB + b] = z;

        float* oz = out + NB * ND;
        oz[b * NL + t] = z;                    // z
        oz[NB * NL + b * NL + t] = am;         // z_mean
        oz[2 * NB * NL + b * NL + t] = av;     // z_log_var
    }
}

// ---------------------------------------------------------------------------
// Decoder: one CTA = (one column d, TM=32 batch rows).
// Phase A: g1t[h][m] = ReLU(sum_l z[b,l]*W[d,l]*gen1_w[h,l])   (SMEM)
// Phase B: per warp, 4 g-columns at a time:
//          g2 = ReLU(g1 . gen2_w[g] + b[g]); xacc += g2 * head_w[d][g]
// Weight loads (gen1/gen2) are warp-uniform broadcasts; SMEM reads are
// lane==m stride-1 -> conflict-free.
// ---------------------------------------------------------------------------
__global__ __launch_bounds__(256, 4) void decoder_kernel(
    const float* __restrict__ Wmat, const float* __restrict__ gen1_w,
    const float* __restrict__ gen2_w, const float* __restrict__ gen2_b,
    const float* __restrict__ head_w, const float* __restrict__ head_b,
    float* __restrict__ out_x)
{
    __shared__ float mT[NL * TM];      // masked, transposed: mT[l*TM + m] (8 KB)
    __shared__ float g1t[NH * TM];     // g1 transposed: g1t[h*TM + m] (38.4 KB)
    __shared__ float head_s[NH];
    __shared__ float bias_s[NH];

    const int d    = blockIdx.x;
    const int b0   = blockIdx.y * TM;
    const int tid  = threadIdx.x;
    const int warp = tid >> 5;
    const int m    = tid & 31;

    for (int i = tid; i < NH; i += 256) {
        head_s[i] = head_w[d * NH + i];
        bias_s[i] = gen2_b[i];
    }
    // maskedT: mT[l*TM + m] = z[b0+m, l] * W[d, l]  (zT read is coalesced)
    for (int idx = tid; idx < NL * TM; idx += 256) {
        int l  = idx >> 5;
        int mm = idx & 31;
        mT[idx] = g_zT[l * NB + b0 + mm] * Wmat[d * NL + l];
    }
    __syncthreads();

    // Phase A: each warp computes rows h = warp, warp+8, ... ; lane = m.
    for (int h = warp; h < NH; h += 8) {
        const float4* w4 = reinterpret_cast<const float4*>(gen1_w + h * NL);
        float acc = 0.f;
        #pragma unroll 4
        for (int l4 = 0; l4 < NL / 4; l4++) {
            float4 w = w4[l4];                 // uniform across warp
            acc += mT[(l4 * 4 + 0) * TM + m] * w.x;
            acc += mT[(l4 * 4 + 1) * TM + m] * w.y;
            acc += mT[(l4 * 4 + 2) * TM + m] * w.z;
            acc += mT[(l4 * 4 + 3) * TM + m] * w.w;
        }
        g1t[h * TM + m] = fmaxf(acc, 0.f);
    }
    __syncthreads();

    // Phase B: warp w covers g-blocks g0 = 4w, 4w+32, ... (4 g's per block)
    float xacc = 0.f;
    for (int g0 = warp * 4; g0 < NH; g0 += 32) {
        float a0 = bias_s[g0 + 0];
        float a1 = bias_s[g0 + 1];
        float a2 = bias_s[g0 + 2];
        float a3 = bias_s[g0 + 3];
        const float4* r0 = reinterpret_cast<const float4*>(gen2_w + (g0 + 0) * NH);
        const float4* r1 = reinterpret_cast<const float4*>(gen2_w + (g0 + 1) * NH);
        const float4* r2 = reinterpret_cast<const float4*>(gen2_w + (g0 + 2) * NH);
        const float4* r3 = reinterpret_cast<const float4*>(gen2_w + (g0 + 3) * NH);
        #pragma unroll 1
        for (int hq = 0; hq < NH / 4; hq++) {
            float4 w0 = r0[hq];                // uniform across warp -> broadcast
            float4 w1 = r1[hq];
            float4 w2 = r2[hq];
            float4 w3 = r3[hq];
            float gA = g1t[(hq * 4 + 0) * TM + m];
            float gB = g1t[(hq * 4 + 1) * TM + m];
            float gC = g1t[(hq * 4 + 2) * TM + m];
            float gD = g1t[(hq * 4 + 3) * TM + m];
            a0 += gA * w0.x + gB * w0.y + gC * w0.z + gD * w0.w;
            a1 += gA * w1.x + gB * w1.y + gC * w1.z + gD * w1.w;
            a2 += gA * w2.x + gB * w2.y + gC * w2.z + gD * w2.w;
            a3 += gA * w3.x + gB * w3.y + gC * w3.z + gD * w3.w;
        }
        xacc += fmaxf(a0, 0.f) * head_s[g0 + 0]
              + fmaxf(a1, 0.f) * head_s[g0 + 1]
              + fmaxf(a2, 0.f) * head_s[g0 + 2]
              + fmaxf(a3, 0.f) * head_s[g0 + 3];
    }

    // Cross-warp reduction over g (reuse mT; phase-A reads fenced by syncthreads above)
    mT[warp * 32 + m] = xacc;
    __syncthreads();
    if (warp == 0) {
        float s = mT[m]       + mT[32 + m]  + mT[64 + m]  + mT[96 + m]
                + mT[128 + m] + mT[160 + m] + mT[192 + m] + mT[224 + m];
        out_x[(b0 + m) * ND + d] = s + head_b[d];
    }
}

extern "C" void kernel_launch(void* const* d_in, const int* in_sizes, int n_in,
                              void* d_out, int out_size)
{
    const float* x      = (const float*)d_in[0];
    const float* eps    = (const float*)d_in[1];
    const float* Wmat   = (const float*)d_in[2];
    const float* enc1_w = (const float*)d_in[3];
    const float* enc1_b = (const float*)d_in[4];
    const float* enc2_w = (const float*)d_in[5];
    const float* enc2_b = (const float*)d_in[6];
    const float* zm_w   = (const float*)d_in[7];
    const float* zm_b   = (const float*)d_in[8];
    const float* zv_w   = (const float*)d_in[9];
    const float* zv_b   = (const float*)d_in[10];
    const float* gen1_w = (const float*)d_in[11];
    const float* gen2_w = (const float*)d_in[12];
    const float* gen2_b = (const float*)d_in[13];
    const float* head_w = (const float*)d_in[14];
    const float* head_b = (const float*)d_in[15];
    float* out = (float*)d_out;

    encoder_kernel<<<NB, 320>>>(x, eps, enc1_w, enc1_b, enc2_w, enc2_b,
                                zm_w, zm_b, zv_w, zv_b, out);
    decoder_kernel<<<dim3(ND, NB / TM), 256>>>(Wmat, gen1_w, gen2_w, gen2_b,
                                               head_w, head_b, out);
}

// round 3
// speedup vs baseline: 1.0657x; 1.0657x over previous
#include <cuda_runtime.h>
#include <cstdint>

#define NB 256
#define ND 512
#define NL 64
#define NH 300
#define NHP 320          // NH padded to chunk multiple
#define CM 128           // batch rows per decoder CTA
#define CP (CM/2)        // 64 float2 pairs
#define GC 32            // g-columns per chunk
#define NCHUNK 10        // ceil(NH/GC)

// SMEM layout (dynamic):
#define OFF_G1    0                         // g1t2: NH*CP float2 = 153600 B
#define OFF_UNION 153600                    // wT (300*33*4=39600) UNION mT2 (64*64*8=32768)
#define OFF_HEAD  (OFF_UNION + 39600)       // 193200, 320 floats
#define OFF_BIAS  (OFF_HEAD + 1280)         // 194480, 320 floats
#define SMEM_BYTES (OFF_BIAS + 1280)        // 195760

__device__ __align__(16) float g_zT[NL * NB];   // z transposed: [l][b]

// ---- f32x2 packed helpers (sm_100+) -------------------------------------
static __device__ __forceinline__ uint64_t dup2(float w) {
    uint64_t r; asm("mov.b64 %0, {%1, %1};" : "=l"(r) : "f"(w)); return r;
}
static __device__ __forceinline__ void fma2(uint64_t &d, uint64_t a, uint64_t b) {
    asm("fma.rn.f32x2 %0, %1, %2, %0;" : "+l"(d) : "l"(a), "l"(b));
}
static __device__ __forceinline__ void unpack2(uint64_t v, float &lo, float &hi) {
    asm("mov.b64 {%0, %1}, %2;" : "=f"(lo), "=f"(hi) : "l"(v));
}
static __device__ __forceinline__ void lds_v2u64(uint64_t &a, uint64_t &b, uint32_t addr) {
    asm volatile("ld.shared.v2.u64 {%0, %1}, [%2];" : "=l"(a), "=l"(b) : "r"(addr));
}

// ---------------------------------------------------------------------------
// Encoder: one CTA per batch row (unchanged from R1 — it passed and is small).
// ---------------------------------------------------------------------------
__global__ __launch_bounds__(320) void encoder_kernel(
    const float* __restrict__ x, const float* __restrict__ eps,
    const float* __restrict__ enc1_w, const float* __restrict__ enc1_b,
    const float* __restrict__ enc2_w, const float* __restrict__ enc2_b,
    const float* __restrict__ zm_w, const float* __restrict__ zm_b,
    const float* __restrict__ zv_w, const float* __restrict__ zv_b,
    float* __restrict__ out)
{
    __shared__ float xs[ND];
    __shared__ float h1[NH];
    __shared__ float h2[NH];

    const int b = blockIdx.x;
    const int t = threadIdx.x;

    for (int i = t; i < ND; i += blockDim.x) xs[i] = x[b * ND + i];
    __syncthreads();

    if (t < NH) {
        float acc = enc1_b[t];
        const float4* w4 = reinterpret_cast<const float4*>(enc1_w + t * ND);
        const float4* x4 = reinterpret_cast<const float4*>(xs);
        #pragma unroll 4
        for (int k = 0; k < ND / 4; k++) {
            float4 w = w4[k], xv = x4[k];
            acc += w.x * xv.x + w.y * xv.y + w.z * xv.z + w.w * xv.w;
        }
        h1[t] = fmaxf(acc, 0.f);
    }
    __syncthreads();

    if (t < NH) {
        float acc = enc2_b[t];
        const float4* w4 = reinterpret_cast<const float4*>(enc2_w + t * NH);
        const float4* h4 = reinterpret_cast<const float4*>(h1);
        #pragma unroll 4
        for (int k = 0; k < NH / 4; k++) {
            float4 w = w4[k], hv = h4[k];
            acc += w.x * hv.x + w.y * hv.y + w.z * hv.z + w.w * hv.w;
        }
        h2[t] = fmaxf(acc, 0.f);
    }
    __syncthreads();

    if (t < NL) {
        float am = zm_b[t];
        float av = zv_b[t];
        const float4* wm4 = reinterpret_cast<const float4*>(zm_w + t * NH);
        const float4* wv4 = reinterpret_cast<const float4*>(zv_w + t * NH);
        const float4* h4  = reinterpret_cast<const float4*>(h2);
        #pragma unroll 5
        for (int k = 0; k < NH / 4; k++) {
            float4 hv = h4[k];
            float4 wm = wm4[k];
            float4 wv = wv4[k];
            am += wm.x * hv.x + wm.y * hv.y + wm.z * hv.z + wm.w * hv.w;
            av += wv.x * hv.x + wv.y * hv.y + wv.z * hv.z + wv.w * hv.w;
        }
        float e = eps[b * NL + t];
        float z = am + e * expf(0.5f * av);

        g_zT[t * NB + b] = z;

        float* oz = out + NB * ND;
        oz[b * NL + t] = z;                    // z
        oz[NB * NL + b * NL + t] = am;         // z_mean
        oz[2 * NB * NL + b * NL + t] = av;     // z_log_var
    }
}

// ---------------------------------------------------------------------------
// Decoder: one CTA = (one column d, CM=128 batch rows). 256 threads, 8 warps.
// Phase A: g1t2[h][mp] = ReLU(sum_l maskedT) as float2 pairs (two b rows).
// Phase B: lane = g-column; gen2_w transposed into SMEM per 32-g chunk;
//          per h: 1 LDS.32 weight + 4 broadcast LDS.128 g1 + 8 FFMA2.
// ---------------------------------------------------------------------------
__global__ __launch_bounds__(256, 1) void decoder_kernel(
    const float* __restrict__ Wmat, const float* __restrict__ gen1_w,
    const float* __restrict__ gen2_w, const float* __restrict__ gen2_b,
    const float* __restrict__ head_w, const float* __restrict__ head_b,
    float* __restrict__ out_x)
{
    extern __shared__ char sm[];
    float2* g1t2   = reinterpret_cast<float2*>(sm + OFF_G1);     // [NH][CP]
    float2* mT2    = reinterpret_cast<float2*>(sm + OFF_UNION);  // [NL][CP] (phase A)
    float*  wTs    = reinterpret_cast<float*>(sm + OFF_UNION);   // [NH][33] (phase B)
    float*  head_s = reinterpret_cast<float*>(sm + OFF_HEAD);
    float*  bias_s = reinterpret_cast<float*>(sm + OFF_BIAS);

    const int d    = blockIdx.x;
    const int b0   = blockIdx.y * CM;
    const int tid  = threadIdx.x;
    const int warp = tid >> 5;
    const int lane = tid & 31;

    // stage head/bias (zero-padded to 320)
    for (int i = tid; i < NHP; i += 256) {
        head_s[i] = (i < NH) ? head_w[d * NH + i] : 0.f;
        bias_s[i] = (i < NH) ? gen2_b[i] : 0.f;
    }
    // stage maskedT pairs: mT2[l][mp] = (z[b0+2mp,l], z[b0+2mp+1,l]) * W[d,l]
    for (int idx = tid; idx < NL * CP; idx += 256) {
        int l  = idx >> 6;
        int mp = idx & 63;
        float2 z = *reinterpret_cast<const float2*>(&g_zT[l * NB + b0 + 2 * mp]);
        float  w = Wmat[d * NL + l];
        mT2[idx] = make_float2(z.x * w, z.y * w);
    }
    __syncthreads();

    // Phase A: 600 items (h, half); each warp takes items warp, warp+8, ...
    for (int item = warp; item < 2 * NH; item += 8) {
        int h  = item >> 1;
        int hh = item & 1;
        const float4* w4 = reinterpret_cast<const float4*>(gen1_w + h * NL);
        const int mbase = hh * 32 + lane;
        uint64_t acc = 0;
        #pragma unroll
        for (int q = 0; q < NL / 4; q++) {
            float4 w = w4[q];                    // warp-uniform LDG.128
            int l = q * 4;
            fma2(acc, dup2(w.x), *reinterpret_cast<uint64_t*>(&mT2[(l + 0) * CP + mbase]));
            fma2(acc, dup2(w.y), *reinterpret_cast<uint64_t*>(&mT2[(l + 1) * CP + mbase]));
            fma2(acc, dup2(w.z), *reinterpret_cast<uint64_t*>(&mT2[(l + 2) * CP + mbase]));
            fma2(acc, dup2(w.w), *reinterpret_cast<uint64_t*>(&mT2[(l + 3) * CP + mbase]));
        }
        float a0, a1; unpack2(acc, a0, a1);
        g1t2[h * CP + mbase] = make_float2(fmaxf(a0, 0.f), fmaxf(a1, 0.f));
    }

    // Phase B: warp owns 8 m-pairs (16 rows); lane = g within the chunk.
    const int mp0 = warp * 8;
    const uint32_t g1base = (uint32_t)__cvta_generic_to_shared(sm) + (uint32_t)(mp0 * 8);

    float xs[16];
    #pragma unroll
    for (int i = 0; i < 16; i++) xs[i] = 0.f;

    for (int c = 0; c < NCHUNK; c++) {
        __syncthreads();   // protects union region (first iter: vs phase-A mT2 reads)
        // stage wT chunk: wTs[h*33 + gl] = gen2_w[g0+gl][h], zero beyond NH
        int g0 = c * GC;
        for (int gl = 0; gl < GC; gl++) {
            int g = g0 + gl;
            if (g < NH) {
                for (int h = tid; h < NH; h += 256)
                    wTs[h * 33 + gl] = gen2_w[g * NH + h];
            } else {
                for (int h = tid; h < NH; h += 256)
                    wTs[h * 33 + gl] = 0.f;
            }
        }
        __syncthreads();

        uint64_t acc0 = 0, acc1 = 0, acc2 = 0, acc3 = 0;
        uint64_t acc4 = 0, acc5 = 0, acc6 = 0, acc7 = 0;
        #pragma unroll 2
        for (int h = 0; h < NH; h++) {
            uint64_t wd = dup2(wTs[h * 33 + lane]);   // conflict-free LDS.32
            uint64_t p0, p1, p2, p3, p4, p5, p6, p7;
            uint32_t a = g1base + (uint32_t)(h * (CP * 8));
            lds_v2u64(p0, p1, a);                     // broadcast LDS.128 x4
            lds_v2u64(p2, p3, a + 16);
            lds_v2u64(p4, p5, a + 32);
            lds_v2u64(p6, p7, a + 48);
            fma2(acc0, wd, p0); fma2(acc1, wd, p1);
            fma2(acc2, wd, p2); fma2(acc3, wd, p3);
            fma2(acc4, wd, p4); fma2(acc5, wd, p5);
            fma2(acc6, wd, p6); fma2(acc7, wd, p7);
        }
        // epilogue: bias + ReLU + head weight, accumulate into xs
        float bb = bias_s[g0 + lane];
        float hs = head_s[g0 + lane];
        uint64_t accs[8] = {acc0, acc1, acc2, acc3, acc4, acc5, acc6, acc7};
        #pragma unroll
        for (int i = 0; i < 8; i++) {
            float v0, v1; unpack2(accs[i], v0, v1);
            xs[2 * i]     += fmaxf(v0 + bb, 0.f) * hs;
            xs[2 * i + 1] += fmaxf(v1 + bb, 0.f) * hs;
        }
    }

    // butterfly reduce over lanes (sum over g)
    #pragma unroll
    for (int off = 16; off > 0; off >>= 1) {
        #pragma unroll
        for (int i = 0; i < 16; i++)
            xs[i] += __shfl_xor_sync(0xFFFFFFFFu, xs[i], off);
    }
    if (lane < 16) {
        int m = warp * 16 + lane;
        out_x[(b0 + m) * ND + d] = xs[lane] + head_b[d];
    }
}

extern "C" void kernel_launch(void* const* d_in, const int* in_sizes, int n_in,
                              void* d_out, int out_size)
{
    const float* x      = (const float*)d_in[0];
    const float* eps    = (const float*)d_in[1];
    const float* Wmat   = (const float*)d_in[2];
    const float* enc1_w = (const float*)d_in[3];
    const float* enc1_b = (const float*)d_in[4];
    const float* enc2_w = (const float*)d_in[5];
    const float* enc2_b = (const float*)d_in[6];
    const float* zm_w   = (const float*)d_in[7];
    const float* zm_b   = (const float*)d_in[8];
    const float* zv_w   = (const float*)d_in[9];
    const float* zv_b   = (const float*)d_in[10];
    const float* gen1_w = (const float*)d_in[11];
    const float* gen2_w = (const float*)d_in[12];
    const float* gen2_b = (const float*)d_in[13];
    const float* head_w = (const float*)d_in[14];
    const float* head_b = (const float*)d_in[15];
    float* out = (float*)d_out;

    static bool attr_set = false;
    if (!attr_set) {
        cudaFuncSetAttribute(decoder_kernel,
                             cudaFuncAttributeMaxDynamicSharedMemorySize, SMEM_BYTES);
        attr_set = true;
    }

    encoder_kernel<<<NB, 320>>>(x, eps, enc1_w, enc1_b, enc2_w, enc2_b,
                                zm_w, zm_b, zv_w, zv_b, out);
    decoder_kernel<<<dim3(ND, NB / CM), 256, SMEM_BYTES>>>(
        Wmat, gen1_w, gen2_w, gen2_b, head_w, head_b, out);
}

// round 7
// speedup vs baseline: 4.6443x; 4.3580x over previous
#include <cuda_runtime.h>
#include <cuda_bf16.h>
#include <cstdint>

#define NB 256
#define ND 512
#define NL 64
#define NH 300
#define CM 64                 // batch rows per decoder CTA

// strides (bytes) for k-major SMEM operands
#define STR1 144              // k=64 padded to 72 bf16
#define STR2 624              // k=304 padded to 312 bf16

// ---- SMEM layout (bytes) --------------------------------------------------
#define OFF_G1HI  0
#define OFF_G1LO  39936                    // 64*312*2
#define OFF_STAGE 79872
#define OFF_MHI   (OFF_STAGE)              // masked hi: 64*72*2 = 9216
#define OFF_MLO   (OFF_STAGE + 9216)
#define OFF_B1HI  (OFF_STAGE + 18432)      // 304*72*2 = 43776
#define OFF_B1LO  (OFF_STAGE + 62208)
// GEMM2 B chunk reuses OFF_STAGE: 160 rows * 624 = 99840 <= 105984
#define OFF_HEAD  185856
#define OFF_BIAS  187136
#define OFF_XRED  188416                   // 128 floats
#define SMEM_TOTAL 188928

__device__ __align__(16) float g_zT[NL * NB];             // z transposed [l][b]
__device__ __align__(16) __nv_bfloat16 g_g1hi[304 * 64];
__device__ __align__(16) __nv_bfloat16 g_g1lo[304 * 64];
__device__ __align__(16) __nv_bfloat16 g_g2hi[320 * 320];
__device__ __align__(16) __nv_bfloat16 g_g2lo[320 * 320];

// ---------------- helpers --------------------------------------------------
static __device__ __forceinline__ uint32_t smem_u32(const void* p) {
    uint32_t a;
    asm("{ .reg .u64 t; cvta.to.shared.u64 t, %1; cvt.u32.u64 %0, t; }" : "=r"(a) : "l"(p));
    return a;
}
static __device__ __forceinline__ void ldsm_x4(uint32_t* r, uint32_t addr) {
    asm volatile("ldmatrix.sync.aligned.m8n8.x4.shared.b16 {%0,%1,%2,%3}, [%4];"
                 : "=r"(r[0]), "=r"(r[1]), "=r"(r[2]), "=r"(r[3]) : "r"(addr));
}
static __device__ __forceinline__ void ldsm_x2(uint32_t* r, uint32_t addr) {
    asm volatile("ldmatrix.sync.aligned.m8n8.x2.shared.b16 {%0,%1}, [%2];"
                 : "=r"(r[0]), "=r"(r[1]) : "r"(addr));
}
static __device__ __forceinline__ void mma_bf16(float* c, const uint32_t* a, const uint32_t* b) {
    asm volatile("mma.sync.aligned.m16n8k16.row.col.f32.bf16.bf16.f32 "
                 "{%0,%1,%2,%3}, {%4,%5,%6,%7}, {%8,%9}, {%0,%1,%2,%3};"
                 : "+f"(c[0]), "+f"(c[1]), "+f"(c[2]), "+f"(c[3])
                 : "r"(a[0]), "r"(a[1]), "r"(a[2]), "r"(a[3]), "r"(b[0]), "r"(b[1]));
}
static __device__ __forceinline__ void split_bf16(float v, __nv_bfloat16& h, __nv_bfloat16& l) {
    h = __float2bfloat16(v);
    l = __float2bfloat16(v - __bfloat162float(h));
}
static __device__ __forceinline__ uint32_t pack_relu_split(float v0, float v1, uint32_t& lopack) {
    v0 = fmaxf(v0, 0.f); v1 = fmaxf(v1, 0.f);
    __nv_bfloat16 h0 = __float2bfloat16(v0);
    __nv_bfloat16 h1 = __float2bfloat16(v1);
    __nv_bfloat16 l0 = __float2bfloat16(v0 - __bfloat162float(h0));
    __nv_bfloat16 l1 = __float2bfloat16(v1 - __bfloat162float(h1));
    lopack = (uint32_t)__bfloat16_as_ushort(l0) | ((uint32_t)__bfloat16_as_ushort(l1) << 16);
    return (uint32_t)__bfloat16_as_ushort(h0) | ((uint32_t)__bfloat16_as_ushort(h1) << 16);
}

// ---------------------------------------------------------------------------
// Prep: split gen1_w / gen2_w into bf16 hi/lo with zero padding.
// ---------------------------------------------------------------------------
__global__ void prep_kernel(const float* __restrict__ g1w, const float* __restrict__ g2w) {
    int idx = blockIdx.x * blockDim.x + threadIdx.x;
    if (idx < 320 * 320) {
        int r = idx / 320, c = idx - r * 320;
        float v = (r < NH && c < NH) ? g2w[r * NH + c] : 0.f;
        __nv_bfloat16 h, l; split_bf16(v, h, l);
        g_g2hi[idx] = h; g_g2lo[idx] = l;
    }
    if (idx < 304 * 64) {
        int r = idx >> 6, c = idx & 63;
        float v = (r < NH) ? g1w[r * NL + c] : 0.f;
        __nv_bfloat16 h, l; split_bf16(v, h, l);
        g_g1hi[idx] = h; g_g1lo[idx] = l;
    }
}

// ---------------------------------------------------------------------------
// Encoder: one CTA per batch row (known-correct).
// ---------------------------------------------------------------------------
__global__ __launch_bounds__(320) void encoder_kernel(
    const float* __restrict__ x, const float* __restrict__ eps,
    const float* __restrict__ enc1_w, const float* __restrict__ enc1_b,
    const float* __restrict__ enc2_w, const float* __restrict__ enc2_b,
    const float* __restrict__ zm_w, const float* __restrict__ zm_b,
    const float* __restrict__ zv_w, const float* __restrict__ zv_b,
    float* __restrict__ out)
{
    __shared__ float xs[ND];
    __shared__ float h1[NH];
    __shared__ float h2[NH];

    const int b = blockIdx.x;
    const int t = threadIdx.x;

    for (int i = t; i < ND; i += blockDim.x) xs[i] = x[b * ND + i];
    __syncthreads();

    if (t < NH) {
        float acc = enc1_b[t];
        const float4* w4 = reinterpret_cast<const float4*>(enc1_w + t * ND);
        const float4* x4 = reinterpret_cast<const float4*>(xs);
        #pragma unroll 4
        for (int k = 0; k < ND / 4; k++) {
            float4 w = w4[k], xv = x4[k];
            acc += w.x * xv.x + w.y * xv.y + w.z * xv.z + w.w * xv.w;
        }
        h1[t] = fmaxf(acc, 0.f);
    }
    __syncthreads();

    if (t < NH) {
        float acc = enc2_b[t];
        const float4* w4 = reinterpret_cast<const float4*>(enc2_w + t * NH);
        const float4* h4 = reinterpret_cast<const float4*>(h1);
        #pragma unroll 4
        for (int k = 0; k < NH / 4; k++) {
            float4 w = w4[k], hv = h4[k];
            acc += w.x * hv.x + w.y * hv.y + w.z * hv.z + w.w * hv.w;
        }
        h2[t] = fmaxf(acc, 0.f);
    }
    __syncthreads();

    if (t < NL) {
        float am = zm_b[t];
        float av = zv_b[t];
        const float4* wm4 = reinterpret_cast<const float4*>(zm_w + t * NH);
        const float4* wv4 = reinterpret_cast<const float4*>(zv_w + t * NH);
        const float4* h4  = reinterpret_cast<const float4*>(h2);
        #pragma unroll 5
        for (int k = 0; k < NH / 4; k++) {
            float4 hv = h4[k];
            float4 wm = wm4[k];
            float4 wv = wv4[k];
            am += wm.x * hv.x + wm.y * hv.y + wm.z * hv.z + wm.w * hv.w;
            av += wv.x * hv.x + wv.y * hv.y + wv.z * hv.z + wv.w * hv.w;
        }
        float e = eps[b * NL + t];
        float z = am + e * expf(0.5f * av);

        g_zT[t * NB + b] = z;

        float* oz = out + NB * ND;
        oz[b * NL + t] = z;
        oz[NB * NL + b * NL + t] = am;
        oz[2 * NB * NL + b * NL + t] = av;
    }
}

// ---------------------------------------------------------------------------
// Decoder: one CTA = (one column d, 64 batch rows). 256 threads, 8 warps.
// Warp = (mw = warp&3 -> 16-row m-block, nh = warp>>2 -> n half).
// GEMM1 (bf16 3-pass mma.sync): g1[64,304] = ReLU(masked @ gen1^T) -> SMEM hi/lo.
// GEMM2 (bf16 3-pass): D[64,320] = g1 @ gen2^T, B staged hi then lo per
//   160-col n-chunk against persistent accumulators; fused epilogue
//   xacc += ReLU(D+bias)*head, quad-shfl + smem reduce, direct STG.
// ---------------------------------------------------------------------------
__global__ __launch_bounds__(256, 1) void decoder_kernel(
    const float* __restrict__ Wmat, const float* __restrict__ gen2_b,
    const float* __restrict__ head_w, const float* __restrict__ head_b,
    float* __restrict__ out_x)
{
    extern __shared__ char sm[];
    const uint32_t sb = smem_u32(sm);
    const int tid = threadIdx.x, warp = tid >> 5, lane = tid & 31;
    const int mw = warp & 3, nh = warp >> 2;
    const int d = blockIdx.x, b0 = blockIdx.y * CM;

    float* head_s = (float*)(sm + OFF_HEAD);
    float* bias_s = (float*)(sm + OFF_BIAS);

    // ---- stage: head/bias, masked hi/lo, gen1 hi/lo ----
    for (int i = tid; i < 320; i += 256) {
        head_s[i] = (i < NH) ? head_w[d * NH + i] : 0.f;
        bias_s[i] = (i < NH) ? gen2_b[i] : 0.f;
    }
    for (int idx = tid; idx < CM * NL; idx += 256) {
        int m = idx & 63, l = idx >> 6;
        float v = g_zT[l * NB + b0 + m] * Wmat[d * NL + l];
        __nv_bfloat16 h, lo; split_bf16(v, h, lo);
        *(__nv_bfloat16*)(sm + OFF_MHI + m * STR1 + l * 2) = h;
        *(__nv_bfloat16*)(sm + OFF_MLO + m * STR1 + l * 2) = lo;
    }
    for (int idx = tid; idx < 304 * 8; idx += 256) {       // 8 uint4 per 64-elem row
        int r = idx >> 3, q = idx & 7;
        *(uint4*)(sm + OFF_B1HI + r * STR1 + q * 16) = ((const uint4*)g_g1hi)[idx];
        *(uint4*)(sm + OFF_B1LO + r * STR1 + q * 16) = ((const uint4*)g_g1lo)[idx];
    }
    __syncthreads();

    // ---- GEMM1: two sub-passes of up to 10 n-tiles ----
    {
        const uint32_t abase = sb + OFF_MHI + (mw * 16 + (lane & 15)) * STR1 + ((lane >> 4) & 1) * 16;
        const uint32_t adelta = OFF_MLO - OFF_MHI;
        #pragma unroll
        for (int sub = 0; sub < 2; sub++) {
            float acc[10][4];
            #pragma unroll
            for (int t = 0; t < 10; t++) { acc[t][0] = acc[t][1] = acc[t][2] = acc[t][3] = 0.f; }
            #pragma unroll
            for (int ks = 0; ks < 4; ks++) {
                uint32_t ahi[4], alo[4], bhi[2], blo[2];
                ldsm_x4(ahi, abase + ks * 32);
                ldsm_x4(alo, abase + adelta + ks * 32);
                #pragma unroll
                for (int t = 0; t < 10; t++) {
                    int tt = sub * 10 + t;
                    if (tt < 19) {
                        uint32_t bb = sb + OFF_B1HI + (nh * 152 + tt * 8 + (lane & 7)) * STR1
                                    + ((lane >> 3) & 1) * 16 + ks * 32;
                        ldsm_x2(bhi, bb);
                        ldsm_x2(blo, bb + (OFF_B1LO - OFF_B1HI));
                        mma_bf16(acc[t], ahi, bhi);
                        mma_bf16(acc[t], alo, bhi);
                        mma_bf16(acc[t], ahi, blo);
                    }
                }
            }
            // ReLU + split + store g1
            #pragma unroll
            for (int t = 0; t < 10; t++) {
                int tt = sub * 10 + t;
                if (tt < 19) {
                    int col = nh * 152 + tt * 8 + 2 * (lane & 3);
                    int r0 = mw * 16 + (lane >> 2);
                    uint32_t lo01, lo23;
                    uint32_t hi01 = pack_relu_split(acc[t][0], acc[t][1], lo01);
                    uint32_t hi23 = pack_relu_split(acc[t][2], acc[t][3], lo23);
                    *(uint32_t*)(sm + OFF_G1HI + r0 * STR2 + col * 2) = hi01;
                    *(uint32_t*)(sm + OFF_G1LO + r0 * STR2 + col * 2) = lo01;
                    *(uint32_t*)(sm + OFF_G1HI + (r0 + 8) * STR2 + col * 2) = hi23;
                    *(uint32_t*)(sm + OFF_G1LO + (r0 + 8) * STR2 + col * 2) = lo23;
                }
            }
        }
    }

    // ---- GEMM2: 2 n-chunks of 160; B staged hi then lo ----
    float xp0 = 0.f, xp1 = 0.f;
    const uint32_t a2base = sb + OFF_G1HI + (mw * 16 + (lane & 15)) * STR2 + ((lane >> 4) & 1) * 16;
    const uint32_t a2delta = OFF_G1LO - OFF_G1HI;

    #pragma unroll 1
    for (int c = 0; c < 2; c++) {
        __syncthreads();   // previous STAGE use / g1 writes complete
        for (int idx = tid; idx < 160 * 38; idx += 256) {
            int r = idx / 38, q = idx - r * 38;
            *(uint4*)(sm + OFF_STAGE + r * STR2 + q * 16) =
                ((const uint4*)(g_g2hi + (c * 160 + r) * 320))[q];
        }
        __syncthreads();

        float acc[10][4];
        #pragma unroll
        for (int t = 0; t < 10; t++) { acc[t][0] = acc[t][1] = acc[t][2] = acc[t][3] = 0.f; }

        #pragma unroll 1
        for (int ks = 0; ks < 19; ks++) {
            uint32_t ahi[4], alo[4], b[2];
            ldsm_x4(ahi, a2base + ks * 32);
            ldsm_x4(alo, a2base + a2delta + ks * 32);
            #pragma unroll
            for (int t = 0; t < 10; t++) {
                uint32_t bb = sb + OFF_STAGE + (nh * 80 + t * 8 + (lane & 7)) * STR2
                            + ((lane >> 3) & 1) * 16 + ks * 32;
                ldsm_x2(b, bb);
                mma_bf16(acc[t], ahi, b);
                mma_bf16(acc[t], alo, b);
            }
        }
        __syncthreads();
        for (int idx = tid; idx < 160 * 38; idx += 256) {
            int r = idx / 38, q = idx - r * 38;
            *(uint4*)(sm + OFF_STAGE + r * STR2 + q * 16) =
                ((const uint4*)(g_g2lo + (c * 160 + r) * 320))[q];
        }
        __syncthreads();
        #pragma unroll 1
        for (int ks = 0; ks < 19; ks++) {
            uint32_t ahi[4], b[2];
            ldsm_x4(ahi, a2base + ks * 32);
            #pragma unroll
            for (int t = 0; t < 10; t++) {
                uint32_t bb = sb + OFF_STAGE + (nh * 80 + t * 8 + (lane & 7)) * STR2
                            + ((lane >> 3) & 1) * 16 + ks * 32;
                ldsm_x2(b, bb);
                mma_bf16(acc[t], ahi, b);
            }
        }

        // fused epilogue for this chunk
        #pragma unroll
        for (int t = 0; t < 10; t++) {
            int g = c * 160 + nh * 80 + t * 8 + 2 * (lane & 3);
            float bb0 = bias_s[g], bb1 = bias_s[g + 1];
            float hh0 = head_s[g], hh1 = head_s[g + 1];
            xp0 = fmaf(fmaxf(acc[t][0] + bb0, 0.f), hh0, xp0);
            xp0 = fmaf(fmaxf(acc[t][1] + bb1, 0.f), hh1, xp0);
            xp1 = fmaf(fmaxf(acc[t][2] + bb0, 0.f), hh0, xp1);
            xp1 = fmaf(fmaxf(acc[t][3] + bb1, 0.f), hh1, xp1);
        }
    }

    // quad reduce (over the 4 col-groups)
    xp0 += __shfl_xor_sync(0xFFFFFFFFu, xp0, 1);
    xp0 += __shfl_xor_sync(0xFFFFFFFFu, xp0, 2);
    xp1 += __shfl_xor_sync(0xFFFFFFFFu, xp1, 1);
    xp1 += __shfl_xor_sync(0xFFFFFFFFu, xp1, 2);

    float* xr = (float*)(sm + OFF_XRED);   // [2 nh][64 rows]
    __syncthreads();
    if ((lane & 3) == 0) {
        int r0 = mw * 16 + (lane >> 2);
        xr[nh * 64 + r0] = xp0;
        xr[nh * 64 + r0 + 8] = xp1;
    }
    __syncthreads();
    if (tid < CM)
        out_x[(b0 + tid) * ND + d] = xr[tid] + xr[64 + tid] + head_b[d];
}

extern "C" void kernel_launch(void* const* d_in, const int* in_sizes, int n_in,
                              void* d_out, int out_size)
{
    const float* x      = (const float*)d_in[0];
    const float* eps    = (const float*)d_in[1];
    const float* Wmat   = (const float*)d_in[2];
    const float* enc1_w = (const float*)d_in[3];
    const float* enc1_b = (const float*)d_in[4];
    const float* enc2_w = (const float*)d_in[5];
    const float* enc2_b = (const float*)d_in[6];
    const float* zm_w   = (const float*)d_in[7];
    const float* zm_b   = (const float*)d_in[8];
    const float* zv_w   = (const float*)d_in[9];
    const float* zv_b   = (const float*)d_in[10];
    const float* gen1_w = (const float*)d_in[11];
    const float* gen2_w = (const float*)d_in[12];
    const float* gen2_b = (const float*)d_in[13];
    const float* head_w = (const float*)d_in[14];
    const float* head_b = (const float*)d_in[15];
    float* out = (float*)d_out;

    static bool attr_set = false;
    if (!attr_set) {
        cudaFuncSetAttribute(decoder_kernel,
                             cudaFuncAttributeMaxDynamicSharedMemorySize, SMEM_TOTAL);
        attr_set = true;
    }

    prep_kernel<<<400, 256>>>(gen1_w, gen2_w);
    encoder_kernel<<<NB, 320>>>(x, eps, enc1_w, enc1_b, enc2_w, enc2_b,
                                zm_w, zm_b, zv_w, zv_b, out);
    decoder_kernel<<<dim3(ND, NB / CM), 256, SMEM_TOTAL>>>(
        Wmat, gen2_b, head_w, head_b, out);
}

// round 11
// speedup vs baseline: 4.8617x; 1.0468x over previous
#include <cuda_runtime.h>
#include <cuda_bf16.h>
#include <cstdint>

#define NB 256
#define ND 512
#define NL 64
#define NH 300
#define CM 64                 // batch rows per decoder CTA

// strides (bytes) for k-major SMEM operands
#define STR1 144              // k=64 padded to 72 bf16
#define STR2 624              // k=304 padded to 312 bf16

// ---- SMEM layout (bytes) --------------------------------------------------
#define OFF_G1HI  0
#define OFF_G1LO  39936                    // 64*312*2
#define OFF_MHI   79872                    // masked hi: 64*72*2 = 9216
#define OFF_MLO   89088
#define OFF_B2    98304                    // two 49920B ping-pong buffers
#define B2BUF     49920
#define OFF_B1HI  OFF_B2                   // gen1 hi (43776 B) overlaps buf0
#define OFF_B1LO  (OFF_B2 + B2BUF)         // gen1 lo overlaps buf1
#define OFF_HEAD  198144
#define OFF_BIAS  199424
#define OFF_XRED  200704                   // 128 floats
#define SMEM_TOTAL 201216

__device__ __align__(16) float g_zT[NL * NB];             // z transposed [l][b]
__device__ __align__(16) __nv_bfloat16 g_g1hi[304 * 64];
__device__ __align__(16) __nv_bfloat16 g_g1lo[304 * 64];
__device__ __align__(16) __nv_bfloat16 g_g2hi[320 * 320];
__device__ __align__(16) __nv_bfloat16 g_g2lo[320 * 320];

// ---------------- helpers --------------------------------------------------
static __device__ __forceinline__ uint32_t smem_u32(const void* p) {
    uint32_t a;
    asm("{ .reg .u64 t; cvta.to.shared.u64 t, %1; cvt.u32.u64 %0, t; }" : "=r"(a) : "l"(p));
    return a;
}
static __device__ __forceinline__ void ldsm_x4(uint32_t* r, uint32_t addr) {
    asm volatile("ldmatrix.sync.aligned.m8n8.x4.shared.b16 {%0,%1,%2,%3}, [%4];"
                 : "=r"(r[0]), "=r"(r[1]), "=r"(r[2]), "=r"(r[3]) : "r"(addr));
}
static __device__ __forceinline__ void ldsm_x2(uint32_t* r, uint32_t addr) {
    asm volatile("ldmatrix.sync.aligned.m8n8.x2.shared.b16 {%0,%1}, [%2];"
                 : "=r"(r[0]), "=r"(r[1]) : "r"(addr));
}
static __device__ __forceinline__ void mma_bf16(float* c, const uint32_t* a, const uint32_t* b) {
    asm volatile("mma.sync.aligned.m16n8k16.row.col.f32.bf16.bf16.f32 "
                 "{%0,%1,%2,%3}, {%4,%5,%6,%7}, {%8,%9}, {%0,%1,%2,%3};"
                 : "+f"(c[0]), "+f"(c[1]), "+f"(c[2]), "+f"(c[3])
                 : "r"(a[0]), "r"(a[1]), "r"(a[2]), "r"(a[3]), "r"(b[0]), "r"(b[1]));
}
static __device__ __forceinline__ void cp16(uint32_t dst, const void* src) {
    asm volatile("cp.async.cg.shared.global [%0], [%1], 16;" :: "r"(dst), "l"(src) : "memory");
}
static __device__ __forceinline__ void cp_commit() { asm volatile("cp.async.commit_group;" ::: "memory"); }
static __device__ __forceinline__ void cp_wait0()  { asm volatile("cp.async.wait_group 0;" ::: "memory"); }
static __device__ __forceinline__ void cp_wait1()  { asm volatile("cp.async.wait_group 1;" ::: "memory"); }

static __device__ __forceinline__ void split_bf16(float v, __nv_bfloat16& h, __nv_bfloat16& l) {
    h = __float2bfloat16(v);
    l = __float2bfloat16(v - __bfloat162float(h));
}
static __device__ __forceinline__ uint32_t pack_relu_split(float v0, float v1, uint32_t& lopack) {
    v0 = fmaxf(v0, 0.f); v1 = fmaxf(v1, 0.f);
    __nv_bfloat16 h0 = __float2bfloat16(v0);
    __nv_bfloat16 h1 = __float2bfloat16(v1);
    __nv_bfloat16 l0 = __float2bfloat16(v0 - __bfloat162float(h0));
    __nv_bfloat16 l1 = __float2bfloat16(v1 - __bfloat162float(h1));
    lopack = (uint32_t)__bfloat16_as_ushort(l0) | ((uint32_t)__bfloat16_as_ushort(l1) << 16);
    return (uint32_t)__bfloat16_as_ushort(h0) | ((uint32_t)__bfloat16_as_ushort(h1) << 16);
}

// ---------------------------------------------------------------------------
// Pre: blocks [0, NB) = encoder (one CTA per batch row);
//      blocks [NB, NB+320) = weight split prep (gen1/gen2 -> bf16 hi/lo).
// ---------------------------------------------------------------------------
__global__ __launch_bounds__(320) void pre_kernel(
    const float* __restrict__ x, const float* __restrict__ eps,
    const float* __restrict__ enc1_w, const float* __restrict__ enc1_b,
    const float* __restrict__ enc2_w, const float* __restrict__ enc2_b,
    const float* __restrict__ zm_w, const float* __restrict__ zm_b,
    const float* __restrict__ zv_w, const float* __restrict__ zv_b,
    const float* __restrict__ g1w, const float* __restrict__ g2w,
    float* __restrict__ out)
{
    if (blockIdx.x >= NB) {
        int idx = (blockIdx.x - NB) * 320 + threadIdx.x;   // [0, 102400)
        {
            int r = idx / 320, c = idx - r * 320;
            float v = (r < NH && c < NH) ? g2w[r * NH + c] : 0.f;
            __nv_bfloat16 h, l; split_bf16(v, h, l);
            g_g2hi[idx] = h; g_g2lo[idx] = l;
        }
        if (idx < 304 * 64) {
            int r = idx >> 6, c = idx & 63;
            float v = (r < NH) ? g1w[r * NL + c] : 0.f;
            __nv_bfloat16 h, l; split_bf16(v, h, l);
            g_g1hi[idx] = h; g_g1lo[idx] = l;
        }
        return;
    }

    __shared__ float xs[ND];
    __shared__ float h1[NH];
    __shared__ float h2[NH];

    const int b = blockIdx.x;
    const int t = threadIdx.x;

    for (int i = t; i < ND; i += blockDim.x) xs[i] = x[b * ND + i];
    __syncthreads();

    if (t < NH) {
        float acc = enc1_b[t];
        const float4* w4 = reinterpret_cast<const float4*>(enc1_w + t * ND);
        const float4* x4 = reinterpret_cast<const float4*>(xs);
        #pragma unroll 4
        for (int k = 0; k < ND / 4; k++) {
            float4 w = w4[k], xv = x4[k];
            acc += w.x * xv.x + w.y * xv.y + w.z * xv.z + w.w * xv.w;
        }
        h1[t] = fmaxf(acc, 0.f);
    }
    __syncthreads();

    if (t < NH) {
        float acc = enc2_b[t];
        const float4* w4 = reinterpret_cast<const float4*>(enc2_w + t * NH);
        const float4* h4 = reinterpret_cast<const float4*>(h1);
        #pragma unroll 4
        for (int k = 0; k < NH / 4; k++) {
            float4 w = w4[k], hv = h4[k];
            acc += w.x * hv.x + w.y * hv.y + w.z * hv.z + w.w * hv.w;
        }
        h2[t] = fmaxf(acc, 0.f);
    }
    __syncthreads();

    if (t < NL) {
        float am = zm_b[t];
        float av = zv_b[t];
        const float4* wm4 = reinterpret_cast<const float4*>(zm_w + t * NH);
        const float4* wv4 = reinterpret_cast<const float4*>(zv_w + t * NH);
        const float4* h4  = reinterpret_cast<const float4*>(h2);
        #pragma unroll 5
        for (int k = 0; k < NH / 4; k++) {
            float4 hv = h4[k];
            float4 wm = wm4[k];
            float4 wv = wv4[k];
            am += wm.x * hv.x + wm.y * hv.y + wm.z * hv.z + wm.w * hv.w;
            av += wv.x * hv.x + wv.y * hv.y + wv.z * hv.z + wv.w * hv.w;
        }
        float e = eps[b * NL + t];
        float z = am + e * expf(0.5f * av);

        g_zT[t * NB + b] = z;

        float* oz = out + NB * ND;
        oz[b * NL + t] = z;
        oz[NB * NL + b * NL + t] = am;
        oz[2 * NB * NL + b * NL + t] = av;
    }
}

// ---------------------------------------------------------------------------
// Decoder: one CTA = (one column d, 64 batch rows). 256 threads, 8 warps.
// Warp = (mw = warp&3 -> 16-row m-block, nh = warp>>2 -> n half).
// GEMM1 (bf16 3-pass mma.sync, gen1 B via cp.async): g1 -> SMEM hi/lo.
// GEMM2: 8 pieces (4 n-chunks x hi/lo) of gen2 B cp.async double-buffered
//   against persistent accumulators; fused epilogue per chunk.
// ---------------------------------------------------------------------------
__global__ __launch_bounds__(256, 1) void decoder_kernel(
    const float* __restrict__ Wmat, const float* __restrict__ gen2_b,
    const float* __restrict__ head_w, const float* __restrict__ head_b,
    float* __restrict__ out_x)
{
    extern __shared__ char sm[];
    const uint32_t sb = smem_u32(sm);
    const int tid = threadIdx.x, warp = tid >> 5, lane = tid & 31;
    const int mw = warp & 3, nh = warp >> 2;
    const int d = blockIdx.x, b0 = blockIdx.y * CM;

    float* head_s = (float*)(sm + OFF_HEAD);
    float* bias_s = (float*)(sm + OFF_BIAS);

    // ---- async stage gen1 hi/lo while computing masked split --------------
    for (int idx = tid; idx < 304 * 8; idx += 256) {
        uint32_t doff = (uint32_t)((idx >> 3) * STR1 + (idx & 7) * 16);
        cp16(sb + OFF_B1HI + doff, (const char*)g_g1hi + idx * 16);
        cp16(sb + OFF_B1LO + doff, (const char*)g_g1lo + idx * 16);
    }
    cp_commit();

    for (int i = tid; i < 320; i += 256) {
        head_s[i] = (i < NH) ? head_w[d * NH + i] : 0.f;
        bias_s[i] = (i < NH) ? gen2_b[i] : 0.f;
    }
    for (int idx = tid; idx < CM * NL; idx += 256) {
        int m = idx & 63, l = idx >> 6;
        float v = g_zT[l * NB + b0 + m] * Wmat[d * NL + l];
        __nv_bfloat16 h, lo; split_bf16(v, h, lo);
        *(__nv_bfloat16*)(sm + OFF_MHI + m * STR1 + l * 2) = h;
        *(__nv_bfloat16*)(sm + OFF_MLO + m * STR1 + l * 2) = lo;
    }
    cp_wait0();
    __syncthreads();

    // ---- GEMM1: two sub-passes of up to 10 n-tiles -------------------------
    {
        const uint32_t abase = sb + OFF_MHI + (mw * 16 + (lane & 15)) * STR1 + ((lane >> 4) & 1) * 16;
        #pragma unroll
        for (int sub = 0; sub < 2; sub++) {
            float acc[10][4];
            #pragma unroll
            for (int t = 0; t < 10; t++) { acc[t][0] = acc[t][1] = acc[t][2] = acc[t][3] = 0.f; }
            #pragma unroll
            for (int ks = 0; ks < 4; ks++) {
                uint32_t ahi[4], alo[4], bhi[2], blo[2];
                ldsm_x4(ahi, abase + ks * 32);
                ldsm_x4(alo, abase + (OFF_MLO - OFF_MHI) + ks * 32);
                #pragma unroll
                for (int t = 0; t < 10; t++) {
                    int tt = sub * 10 + t;
                    if (tt < 19) {
                        uint32_t bb = sb + OFF_B1HI + (nh * 152 + tt * 8 + (lane & 7)) * STR1
                                    + ((lane >> 3) & 1) * 16 + ks * 32;
                        ldsm_x2(bhi, bb);
                        ldsm_x2(blo, bb + B2BUF);
                        mma_bf16(acc[t], ahi, bhi);
                        mma_bf16(acc[t], alo, bhi);
                        mma_bf16(acc[t], ahi, blo);
                    }
                }
            }
            // ReLU + split + store g1
            #pragma unroll
            for (int t = 0; t < 10; t++) {
                int tt = sub * 10 + t;
                if (tt < 19) {
                    int col = nh * 152 + tt * 8 + 2 * (lane & 3);
                    int r0 = mw * 16 + (lane >> 2);
                    uint32_t lo01, lo23;
                    uint32_t hi01 = pack_relu_split(acc[t][0], acc[t][1], lo01);
                    uint32_t hi23 = pack_relu_split(acc[t][2], acc[t][3], lo23);
                    *(uint32_t*)(sm + OFF_G1HI + r0 * STR2 + col * 2) = hi01;
                    *(uint32_t*)(sm + OFF_G1LO + r0 * STR2 + col * 2) = lo01;
                    *(uint32_t*)(sm + OFF_G1HI + (r0 + 8) * STR2 + col * 2) = hi23;
                    *(uint32_t*)(sm + OFF_G1LO + (r0 + 8) * STR2 + col * 2) = lo23;
                }
            }
        }
    }
    __syncthreads();   // B1 reads + g1 writes complete

    // ---- GEMM2: 8 pieces (chunk c = p>>1; hv = p&1), double-buffered -------
    // piece p -> buf[p&1]; hi piece: Ahi*B + Alo*B; lo piece: Ahi*B.
    {
        // issue piece 0 and piece 1
        #pragma unroll
        for (int p0 = 0; p0 < 2; p0++) {
            const __nv_bfloat16* src = (p0 ? g_g2lo : g_g2hi);   // c=0
            for (int idx = tid; idx < 80 * 38; idx += 256) {
                int r = idx / 38, q = idx - r * 38;
                cp16(sb + OFF_B2 + p0 * B2BUF + r * STR2 + q * 16,
                     (const char*)src + r * 640 + q * 16);
            }
            cp_commit();
        }

        float xp0 = 0.f, xp1 = 0.f;
        float acc[5][4];
        const uint32_t a2base = sb + OFF_G1HI + (mw * 16 + (lane & 15)) * STR2 + ((lane >> 4) & 1) * 16;

        #pragma unroll 1
        for (int p = 0; p < 8; p++) {
            if (p < 7) cp_wait1(); else cp_wait0();
            __syncthreads();

            const int c = p >> 1, hv = p & 1;
            const uint32_t bufb = sb + OFF_B2 + (uint32_t)((p & 1) * B2BUF);

            if (!hv) {
                #pragma unroll
                for (int t = 0; t < 5; t++) { acc[t][0] = acc[t][1] = acc[t][2] = acc[t][3] = 0.f; }
                #pragma unroll 1
                for (int ks = 0; ks < 19; ks++) {
                    uint32_t ahi[4], alo[4], b[2];
                    ldsm_x4(ahi, a2base + ks * 32);
                    ldsm_x4(alo, a2base + (OFF_G1LO - OFF_G1HI) + ks * 32);
                    #pragma unroll
                    for (int t = 0; t < 5; t++) {
                        ldsm_x2(b, bufb + (nh * 40 + t * 8 + (lane & 7)) * STR2
                                  + ((lane >> 3) & 1) * 16 + ks * 32);
                        mma_bf16(acc[t], ahi, b);
                        mma_bf16(acc[t], alo, b);
                    }
                }
            } else {
                #pragma unroll 1
                for (int ks = 0; ks < 19; ks++) {
                    uint32_t ahi[4], b[2];
                    ldsm_x4(ahi, a2base + ks * 32);
                    #pragma unroll
                    for (int t = 0; t < 5; t++) {
                        ldsm_x2(b, bufb + (nh * 40 + t * 8 + (lane & 7)) * STR2
                                  + ((lane >> 3) & 1) * 16 + ks * 32);
                        mma_bf16(acc[t], ahi, b);
                    }
                }
                // fused epilogue for chunk c
                #pragma unroll
                for (int t = 0; t < 5; t++) {
                    int g = c * 80 + nh * 40 + t * 8 + 2 * (lane & 3);
                    float bb0 = bias_s[g], bb1 = bias_s[g + 1];
                    float hh0 = head_s[g], hh1 = head_s[g + 1];
                    xp0 = fmaf(fmaxf(acc[t][0] + bb0, 0.f), hh0, xp0);
                    xp0 = fmaf(fmaxf(acc[t][1] + bb1, 0.f), hh1, xp0);
                    xp1 = fmaf(fmaxf(acc[t][2] + bb0, 0.f), hh0, xp1);
                    xp1 = fmaf(fmaxf(acc[t][3] + bb1, 0.f), hh1, xp1);
                }
            }

            if (p + 2 < 8) {
                __syncthreads();   // all warps done reading buf[p&1]
                const int pn = p + 2;
                const __nv_bfloat16* src = ((pn & 1) ? g_g2lo : g_g2hi) + (pn >> 1) * 80 * 320;
                for (int idx = tid; idx < 80 * 38; idx += 256) {
                    int r = idx / 38, q = idx - r * 38;
                    cp16(bufb + r * STR2 + q * 16, (const char*)src + r * 640 + q * 16);
                }
                cp_commit();
            }
        }

        // quad reduce (over the 4 col-groups)
        xp0 += __shfl_xor_sync(0xFFFFFFFFu, xp0, 1);
        xp0 += __shfl_xor_sync(0xFFFFFFFFu, xp0, 2);
        xp1 += __shfl_xor_sync(0xFFFFFFFFu, xp1, 1);
        xp1 += __shfl_xor_sync(0xFFFFFFFFu, xp1, 2);

        float* xr = (float*)(sm + OFF_XRED);   // [2 nh][64 rows]
        __syncthreads();
        if ((lane & 3) == 0) {
            int r0 = mw * 16 + (lane >> 2);
            xr[nh * 64 + r0] = xp0;
            xr[nh * 64 + r0 + 8] = xp1;
        }
        __syncthreads();
        if (tid < CM)
            out_x[(b0 + tid) * ND + d] = xr[tid] + xr[64 + tid] + head_b[d];
    }
}

extern "C" void kernel_launch(void* const* d_in, const int* in_sizes, int n_in,
                              void* d_out, int out_size)
{
    const float* x      = (const float*)d_in[0];
    const float* eps    = (const float*)d_in[1];
    const float* Wmat   = (const float*)d_in[2];
    const float* enc1_w = (const float*)d_in[3];
    const float* enc1_b = (const float*)d_in[4];
    const float* enc2_w = (const float*)d_in[5];
    const float* enc2_b = (const float*)d_in[6];
    const float* zm_w   = (const float*)d_in[7];
    const float* zm_b   = (const float*)d_in[8];
    const float* zv_w   = (const float*)d_in[9];
    const float* zv_b   = (const float*)d_in[10];
    const float* gen1_w = (const float*)d_in[11];
    const float* gen2_w = (const float*)d_in[12];
    const float* gen2_b = (const float*)d_in[13];
    const float* head_w = (const float*)d_in[14];
    const float* head_b = (const float*)d_in[15];
    float* out = (float*)d_out;

    static bool attr_set = false;
    if (!attr_set) {
        cudaFuncSetAttribute(decoder_kernel,
                             cudaFuncAttributeMaxDynamicSharedMemorySize, SMEM_TOTAL);
        attr_set = true;
    }

    pre_kernel<<<NB + 320, 320>>>(x, eps, enc1_w, enc1_b, enc2_w, enc2_b,
                                  zm_w, zm_b, zv_w, zv_b, gen1_w, gen2_w, out);
    decoder_kernel<<<dim3(ND, NB / CM), 256, SMEM_TOTAL>>>(
        Wmat, gen2_b, head_w, head_b, out);
}

// round 12
// speedup vs baseline: 6.3707x; 1.3104x over previous
#include <cuda_runtime.h>
#include <cuda_fp16.h>
#include <cstdint>

#define NB 256
#define ND 512
#define NL 64
#define NH 300
#define CM 64                 // batch rows per decoder CTA

// strides (bytes) for k-major SMEM operands
#define STR1 144              // k=64 padded to 72 halves
#define STR2 624              // k=304 padded to 312 halves

// ---- SMEM layout (bytes) --------------------------------------------------
#define OFF_G1HI  0
#define OFF_G1LO  39936                    // 64*312*2
#define OFF_MHI   79872                    // masked hi: 64*72*2 = 9216
#define OFF_MLO   89088
#define OFF_B2    98304                    // two 49920B ping-pong buffers
#define B2BUF     49920
#define OFF_B1HI  OFF_B2                   // gen1 hi (43776 B) overlaps buf0
#define OFF_B1LO  (OFF_B2 + B2BUF)         // gen1 lo overlaps buf1
#define OFF_HEAD  198144
#define OFF_BIAS  199424
#define OFF_XRED  200704                   // 128 floats
#define SMEM_TOTAL 201216

__device__ __align__(16) float g_zT[NL * NB];       // z transposed [l][b]
__device__ __align__(16) __half g_g1hi[304 * 64];
__device__ __align__(16) __half g_g1lo[304 * 64];
__device__ __align__(16) __half g_g2hi[320 * 320];  // gen2 hi only (2-term GEMM2)

// ---------------- helpers --------------------------------------------------
static __device__ __forceinline__ uint32_t smem_u32(const void* p) {
    uint32_t a;
    asm("{ .reg .u64 t; cvta.to.shared.u64 t, %1; cvt.u32.u64 %0, t; }" : "=r"(a) : "l"(p));
    return a;
}
static __device__ __forceinline__ void ldsm_x4(uint32_t* r, uint32_t addr) {
    asm volatile("ldmatrix.sync.aligned.m8n8.x4.shared.b16 {%0,%1,%2,%3}, [%4];"
                 : "=r"(r[0]), "=r"(r[1]), "=r"(r[2]), "=r"(r[3]) : "r"(addr));
}
static __device__ __forceinline__ void ldsm_x2(uint32_t* r, uint32_t addr) {
    asm volatile("ldmatrix.sync.aligned.m8n8.x2.shared.b16 {%0,%1}, [%2];"
                 : "=r"(r[0]), "=r"(r[1]) : "r"(addr));
}
static __device__ __forceinline__ void mma_f16(float* c, const uint32_t* a, const uint32_t* b) {
    asm volatile("mma.sync.aligned.m16n8k16.row.col.f32.f16.f16.f32 "
                 "{%0,%1,%2,%3}, {%4,%5,%6,%7}, {%8,%9}, {%0,%1,%2,%3};"
                 : "+f"(c[0]), "+f"(c[1]), "+f"(c[2]), "+f"(c[3])
                 : "r"(a[0]), "r"(a[1]), "r"(a[2]), "r"(a[3]), "r"(b[0]), "r"(b[1]));
}
static __device__ __forceinline__ void cp16(uint32_t dst, const void* src) {
    asm volatile("cp.async.cg.shared.global [%0], [%1], 16;" :: "r"(dst), "l"(src) : "memory");
}
static __device__ __forceinline__ void cp_commit() { asm volatile("cp.async.commit_group;" ::: "memory"); }
static __device__ __forceinline__ void cp_wait0()  { asm volatile("cp.async.wait_group 0;" ::: "memory"); }
static __device__ __forceinline__ void cp_wait1()  { asm volatile("cp.async.wait_group 1;" ::: "memory"); }

static __device__ __forceinline__ void split_f16(float v, __half& h, __half& l) {
    h = __float2half_rn(v);
    l = __float2half_rn(v - __half2float(h));
}
static __device__ __forceinline__ uint32_t pack_relu_split(float v0, float v1, uint32_t& lopack) {
    v0 = fmaxf(v0, 0.f); v1 = fmaxf(v1, 0.f);
    __half h0 = __float2half_rn(v0);
    __half h1 = __float2half_rn(v1);
    __half l0 = __float2half_rn(v0 - __half2float(h0));
    __half l1 = __float2half_rn(v1 - __half2float(h1));
    lopack = (uint32_t)__half_as_ushort(l0) | ((uint32_t)__half_as_ushort(l1) << 16);
    return (uint32_t)__half_as_ushort(h0) | ((uint32_t)__half_as_ushort(h1) << 16);
}

// ---------------------------------------------------------------------------
// Pre: blocks [0, NB) = encoder (one CTA per batch row);
//      blocks [NB, NB+320) = weight split prep (gen1 hi/lo, gen2 hi).
// ---------------------------------------------------------------------------
__global__ __launch_bounds__(320) void pre_kernel(
    const float* __restrict__ x, const float* __restrict__ eps,
    const float* __restrict__ enc1_w, const float* __restrict__ enc1_b,
    const float* __restrict__ enc2_w, const float* __restrict__ enc2_b,
    const float* __restrict__ zm_w, const float* __restrict__ zm_b,
    const float* __restrict__ zv_w, const float* __restrict__ zv_b,
    const float* __restrict__ g1w, const float* __restrict__ g2w,
    float* __restrict__ out)
{
    if (blockIdx.x >= NB) {
        int idx = (blockIdx.x - NB) * 320 + threadIdx.x;   // [0, 102400)
        {
            int r = idx / 320, c = idx - r * 320;
            float v = (r < NH && c < NH) ? g2w[r * NH + c] : 0.f;
            g_g2hi[idx] = __float2half_rn(v);
        }
        if (idx < 304 * 64) {
            int r = idx >> 6, c = idx & 63;
            float v = (r < NH) ? g1w[r * NL + c] : 0.f;
            __half h, l; split_f16(v, h, l);
            g_g1hi[idx] = h; g_g1lo[idx] = l;
        }
        return;
    }

    __shared__ float xs[ND];
    __shared__ float h1[NH];
    __shared__ float h2[NH];

    const int b = blockIdx.x;
    const int t = threadIdx.x;

    for (int i = t; i < ND; i += blockDim.x) xs[i] = x[b * ND + i];
    __syncthreads();

    if (t < NH) {
        float acc = enc1_b[t];
        const float4* w4 = reinterpret_cast<const float4*>(enc1_w + t * ND);
        const float4* x4 = reinterpret_cast<const float4*>(xs);
        #pragma unroll 4
        for (int k = 0; k < ND / 4; k++) {
            float4 w = w4[k], xv = x4[k];
            acc += w.x * xv.x + w.y * xv.y + w.z * xv.z + w.w * xv.w;
        }
        h1[t] = fmaxf(acc, 0.f);
    }
    __syncthreads();

    if (t < NH) {
        float acc = enc2_b[t];
        const float4* w4 = reinterpret_cast<const float4*>(enc2_w + t * NH);
        const float4* h4 = reinterpret_cast<const float4*>(h1);
        #pragma unroll 4
        for (int k = 0; k < NH / 4; k++) {
            float4 w = w4[k], hv = h4[k];
            acc += w.x * hv.x + w.y * hv.y + w.z * hv.z + w.w * hv.w;
        }
        h2[t] = fmaxf(acc, 0.f);
    }
    __syncthreads();

    if (t < NL) {
        float am = zm_b[t];
        float av = zv_b[t];
        const float4* wm4 = reinterpret_cast<const float4*>(zm_w + t * NH);
        const float4* wv4 = reinterpret_cast<const float4*>(zv_w + t * NH);
        const float4* h4  = reinterpret_cast<const float4*>(h2);
        #pragma unroll 5
        for (int k = 0; k < NH / 4; k++) {
            float4 hv = h4[k];
            float4 wm = wm4[k];
            float4 wv = wv4[k];
            am += wm.x * hv.x + wm.y * hv.y + wm.z * hv.z + wm.w * hv.w;
            av += wv.x * hv.x + wv.y * hv.y + wv.z * hv.z + wv.w * hv.w;
        }
        float e = eps[b * NL + t];
        float z = am + e * expf(0.5f * av);

        g_zT[t * NB + b] = z;

        float* oz = out + NB * ND;
        oz[b * NL + t] = z;
        oz[NB * NL + b * NL + t] = am;
        oz[2 * NB * NL + b * NL + t] = av;
    }
}

// ---------------------------------------------------------------------------
// Decoder: one CTA = (one column d, 64 batch rows). 256 threads, 8 warps.
// Warp = (mw = warp&3 -> 16-row m-block, nh = warp>>2 -> n half).
// GEMM1 (fp16 3-term mma.sync, gen1 via cp.async): g1 -> SMEM hi/lo.
// GEMM2 (fp16 2-term: Ahi*Bhi + Alo*Bhi): 4 hi-only pieces of gen2 B,
//   cp.async double-buffered; fused epilogue per piece.
// ---------------------------------------------------------------------------
__global__ __launch_bounds__(256, 1) void decoder_kernel(
    const float* __restrict__ Wmat, const float* __restrict__ gen2_b,
    const float* __restrict__ head_w, const float* __restrict__ head_b,
    float* __restrict__ out_x)
{
    extern __shared__ char sm[];
    const uint32_t sb = smem_u32(sm);
    const int tid = threadIdx.x, warp = tid >> 5, lane = tid & 31;
    const int mw = warp & 3, nh = warp >> 2;
    const int d = blockIdx.x, b0 = blockIdx.y * CM;

    float* head_s = (float*)(sm + OFF_HEAD);
    float* bias_s = (float*)(sm + OFF_BIAS);

    // ---- async stage gen1 hi/lo while computing masked split --------------
    for (int idx = tid; idx < 304 * 8; idx += 256) {
        uint32_t doff = (uint32_t)((idx >> 3) * STR1 + (idx & 7) * 16);
        cp16(sb + OFF_B1HI + doff, (const char*)g_g1hi + idx * 16);
        cp16(sb + OFF_B1LO + doff, (const char*)g_g1lo + idx * 16);
    }
    cp_commit();

    for (int i = tid; i < 320; i += 256) {
        head_s[i] = (i < NH) ? head_w[d * NH + i] : 0.f;
        bias_s[i] = (i < NH) ? gen2_b[i] : 0.f;
    }
    for (int idx = tid; idx < CM * NL; idx += 256) {
        int m = idx & 63, l = idx >> 6;
        float v = g_zT[l * NB + b0 + m] * Wmat[d * NL + l];
        __half h, lo; split_f16(v, h, lo);
        *(__half*)(sm + OFF_MHI + m * STR1 + l * 2) = h;
        *(__half*)(sm + OFF_MLO + m * STR1 + l * 2) = lo;
    }
    cp_wait0();
    __syncthreads();

    // ---- GEMM1: two sub-passes of up to 10 n-tiles (3-term fp16) ----------
    {
        const uint32_t abase = sb + OFF_MHI + (mw * 16 + (lane & 15)) * STR1 + ((lane >> 4) & 1) * 16;
        #pragma unroll
        for (int sub = 0; sub < 2; sub++) {
            float acc[10][4];
            #pragma unroll
            for (int t = 0; t < 10; t++) { acc[t][0] = acc[t][1] = acc[t][2] = acc[t][3] = 0.f; }
            #pragma unroll
            for (int ks = 0; ks < 4; ks++) {
                uint32_t ahi[4], alo[4], bhi[2], blo[2];
                ldsm_x4(ahi, abase + ks * 32);
                ldsm_x4(alo, abase + (OFF_MLO - OFF_MHI) + ks * 32);
                #pragma unroll
                for (int t = 0; t < 10; t++) {
                    int tt = sub * 10 + t;
                    if (tt < 19) {
                        uint32_t bb = sb + OFF_B1HI + (nh * 152 + tt * 8 + (lane & 7)) * STR1
                                    + ((lane >> 3) & 1) * 16 + ks * 32;
                        ldsm_x2(bhi, bb);
                        ldsm_x2(blo, bb + B2BUF);
                        mma_f16(acc[t], ahi, bhi);
                        mma_f16(acc[t], alo, bhi);
                        mma_f16(acc[t], ahi, blo);
                    }
                }
            }
            // ReLU + split + store g1
            #pragma unroll
            for (int t = 0; t < 10; t++) {
                int tt = sub * 10 + t;
                if (tt < 19) {
                    int col = nh * 152 + tt * 8 + 2 * (lane & 3);
                    int r0 = mw * 16 + (lane >> 2);
                    uint32_t lo01, lo23;
                    uint32_t hi01 = pack_relu_split(acc[t][0], acc[t][1], lo01);
                    uint32_t hi23 = pack_relu_split(acc[t][2], acc[t][3], lo23);
                    *(uint32_t*)(sm + OFF_G1HI + r0 * STR2 + col * 2) = hi01;
                    *(uint32_t*)(sm + OFF_G1LO + r0 * STR2 + col * 2) = lo01;
                    *(uint32_t*)(sm + OFF_G1HI + (r0 + 8) * STR2 + col * 2) = hi23;
                    *(uint32_t*)(sm + OFF_G1LO + (r0 + 8) * STR2 + col * 2) = lo23;
                }
            }
        }
    }
    __syncthreads();   // B1 reads + g1 writes complete

    // ---- GEMM2: 4 hi-only pieces of 80 cols, double-buffered --------------
    {
        // issue piece 0 and piece 1
        #pragma unroll
        for (int p0 = 0; p0 < 2; p0++) {
            const __half* src = g_g2hi + p0 * 80 * 320;
            for (int idx = tid; idx < 80 * 38; idx += 256) {
                int r = idx / 38, q = idx - r * 38;
                cp16(sb + OFF_B2 + p0 * B2BUF + r * STR2 + q * 16,
                     (const char*)src + r * 640 + q * 16);
            }
            cp_commit();
        }

        float xp0 = 0.f, xp1 = 0.f;
        float acc[5][4];
        const uint32_t a2base = sb + OFF_G1HI + (mw * 16 + (lane & 15)) * STR2 + ((lane >> 4) & 1) * 16;

        #pragma unroll 1
        for (int p = 0; p < 4; p++) {
            if (p < 3) cp_wait1(); else cp_wait0();
            __syncthreads();

            const uint32_t bufb = sb + OFF_B2 + (uint32_t)((p & 1) * B2BUF);

            #pragma unroll
            for (int t = 0; t < 5; t++) { acc[t][0] = acc[t][1] = acc[t][2] = acc[t][3] = 0.f; }
            #pragma unroll 1
            for (int ks = 0; ks < 19; ks++) {
                uint32_t ahi[4], alo[4], b[2];
                ldsm_x4(ahi, a2base + ks * 32);
                ldsm_x4(alo, a2base + (OFF_G1LO - OFF_G1HI) + ks * 32);
                #pragma unroll
                for (int t = 0; t < 5; t++) {
                    ldsm_x2(b, bufb + (nh * 40 + t * 8 + (lane & 7)) * STR2
                              + ((lane >> 3) & 1) * 16 + ks * 32);
                    mma_f16(acc[t], ahi, b);
                    mma_f16(acc[t], alo, b);
                }
            }
            // fused epilogue for piece p (cols p*80 ...)
            #pragma unroll
            for (int t = 0; t < 5; t++) {
                int g = p * 80 + nh * 40 + t * 8 + 2 * (lane & 3);
                float bb0 = bias_s[g], bb1 = bias_s[g + 1];
                float hh0 = head_s[g], hh1 = head_s[g + 1];
                xp0 = fmaf(fmaxf(acc[t][0] + bb0, 0.f), hh0, xp0);
                xp0 = fmaf(fmaxf(acc[t][1] + bb1, 0.f), hh1, xp0);
                xp1 = fmaf(fmaxf(acc[t][2] + bb0, 0.f), hh0, xp1);
                xp1 = fmaf(fmaxf(acc[t][3] + bb1, 0.f), hh1, xp1);
            }

            if (p + 2 < 4) {
                __syncthreads();   // all warps done reading buf[p&1]
                const __half* src = g_g2hi + (p + 2) * 80 * 320;
                for (int idx = tid; idx < 80 * 38; idx += 256) {
                    int r = idx / 38, q = idx - r * 38;
                    cp16(bufb + r * STR2 + q * 16, (const char*)src + r * 640 + q * 16);
                }
                cp_commit();
            }
        }

        // quad reduce (over the 4 col-groups)
        xp0 += __shfl_xor_sync(0xFFFFFFFFu, xp0, 1);
        xp0 += __shfl_xor_sync(0xFFFFFFFFu, xp0, 2);
        xp1 += __shfl_xor_sync(0xFFFFFFFFu, xp1, 1);
        xp1 += __shfl_xor_sync(0xFFFFFFFFu, xp1, 2);

        float* xr = (float*)(sm + OFF_XRED);   // [2 nh][64 rows]
        __syncthreads();
        if ((lane & 3) == 0) {
            int r0 = mw * 16 + (lane >> 2);
            xr[nh * 64 + r0] = xp0;
            xr[nh * 64 + r0 + 8] = xp1;
        }
        __syncthreads();
        if (tid < CM)
            out_x[(b0 + tid) * ND + d] = xr[tid] + xr[64 + tid] + head_b[d];
    }
}

extern "C" void kernel_launch(void* const* d_in, const int* in_sizes, int n_in,
                              void* d_out, int out_size)
{
    const float* x      = (const float*)d_in[0];
    const float* eps    = (const float*)d_in[1];
    const float* Wmat   = (const float*)d_in[2];
    const float* enc1_w = (const float*)d_in[3];
    const float* enc1_b = (const float*)d_in[4];
    const float* enc2_w = (const float*)d_in[5];
    const float* enc2_b = (const float*)d_in[6];
    const float* zm_w   = (const float*)d_in[7];
    const float* zm_b   = (const float*)d_in[8];
    const float* zv_w   = (const float*)d_in[9];
    const float* zv_b   = (const float*)d_in[10];
    const float* gen1_w = (const float*)d_in[11];
    const float* gen2_w = (const float*)d_in[12];
    const float* gen2_b = (const float*)d_in[13];
    const float* head_w = (const float*)d_in[14];
    const float* head_b = (const float*)d_in[15];
    float* out = (float*)d_out;

    static bool attr_set = false;
    if (!attr_set) {
        cudaFuncSetAttribute(decoder_kernel,
                             cudaFuncAttributeMaxDynamicSharedMemorySize, SMEM_TOTAL);
        attr_set = true;
    }

    pre_kernel<<<NB + 320, 320>>>(x, eps, enc1_w, enc1_b, enc2_w, enc2_b,
                                  zm_w, zm_b, zv_w, zv_b, gen1_w, gen2_w, out);
    decoder_kernel<<<dim3(ND, NB / CM), 256, SMEM_TOTAL>>>(
        Wmat, gen2_b, head_w, head_b, out);
}

// round 14
// speedup vs baseline: 8.1265x; 1.2756x over previous
#include <cuda_runtime.h>
#include <cuda_fp16.h>
#include <cstdint>

#define NB 256
#define ND 512
#define NL 64
#define NH 300
#define CM 64                 // batch rows per decoder CTA

// strides (bytes) for k-major SMEM operands
#define STR1 144              // k=64 padded to 72 halves
#define STR2 624              // k=304 padded to 312 halves

// ---- decoder SMEM layout (bytes) ------------------------------------------
#define OFF_G1    0                        // g1 hi fp16 [64][312h] = 39936
#define OFF_MHI   39936                    // masked hi 64*144 = 9216
#define OFF_MLO   49152
#define OFF_B     58368                    // two ping-pong buffers
#define BUFSZ     24960                    // fits B1 piece (23040) and B2 piece (24960)
#define B1LO_OFF  11520                    // lo half offset within a B1 piece (80*144)
#define OFF_HEAD  108288                   // 320 floats
#define OFF_BIAS  109568                   // 320 floats
#define OFF_XRED  110848                   // 128 floats
#define SMEM_TOTAL 111360

__device__ __align__(16) float g_zT[NL * NB];       // z transposed [l][b]
__device__ __align__(16) __half g_g1hi[320 * 64];   // padded to 320 rows
__device__ __align__(16) __half g_g1lo[320 * 64];
__device__ __align__(16) __half g_g2hi[320 * 320];  // gen2 hi only

// ---------------- helpers --------------------------------------------------
static __device__ __forceinline__ uint32_t smem_u32(const void* p) {
    uint32_t a;
    asm("{ .reg .u64 t; cvta.to.shared.u64 t, %1; cvt.u32.u64 %0, t; }" : "=r"(a) : "l"(p));
    return a;
}
static __device__ __forceinline__ void ldsm_x4(uint32_t* r, uint32_t addr) {
    asm volatile("ldmatrix.sync.aligned.m8n8.x4.shared.b16 {%0,%1,%2,%3}, [%4];"
                 : "=r"(r[0]), "=r"(r[1]), "=r"(r[2]), "=r"(r[3]) : "r"(addr));
}
static __device__ __forceinline__ void ldsm_x2(uint32_t* r, uint32_t addr) {
    asm volatile("ldmatrix.sync.aligned.m8n8.x2.shared.b16 {%0,%1}, [%2];"
                 : "=r"(r[0]), "=r"(r[1]) : "r"(addr));
}
static __device__ __forceinline__ void mma_f16(float* c, const uint32_t* a, const uint32_t* b) {
    asm volatile("mma.sync.aligned.m16n8k16.row.col.f32.f16.f16.f32 "
                 "{%0,%1,%2,%3}, {%4,%5,%6,%7}, {%8,%9}, {%0,%1,%2,%3};"
                 : "+f"(c[0]), "+f"(c[1]), "+f"(c[2]), "+f"(c[3])
                 : "r"(a[0]), "r"(a[1]), "r"(a[2]), "r"(a[3]), "r"(b[0]), "r"(b[1]));
}
static __device__ __forceinline__ void cp16(uint32_t dst, const void* src) {
    asm volatile("cp.async.cg.shared.global [%0], [%1], 16;" :: "r"(dst), "l"(src) : "memory");
}
static __device__ __forceinline__ void cp_commit() { asm volatile("cp.async.commit_group;" ::: "memory"); }
static __device__ __forceinline__ void cp_wait0()  { asm volatile("cp.async.wait_group 0;" ::: "memory"); }
static __device__ __forceinline__ void cp_wait1()  { asm volatile("cp.async.wait_group 1;" ::: "memory"); }

static __device__ __forceinline__ void split_f16(float v, __half& h, __half& l) {
    h = __float2half_rn(v);
    l = __float2half_rn(v - __half2float(h));
}
static __device__ __forceinline__ uint32_t pack_relu2(float v0, float v1) {
    __half h0 = __float2half_rn(fmaxf(v0, 0.f));
    __half h1 = __float2half_rn(fmaxf(v1, 0.f));
    return (uint32_t)__half_as_ushort(h0) | ((uint32_t)__half_as_ushort(h1) << 16);
}

// ---------------------------------------------------------------------------
// Pre: blocks [0, 32) = encoder (8 batch rows per CTA, weights streamed once);
//      blocks [32, 352) = weight prep (gen1 hi/lo padded to 320 rows, gen2 hi).
// ---------------------------------------------------------------------------
__global__ __launch_bounds__(320) void pre_kernel(
    const float* __restrict__ x, const float* __restrict__ eps,
    const float* __restrict__ enc1_w, const float* __restrict__ enc1_b,
    const float* __restrict__ enc2_w, const float* __restrict__ enc2_b,
    const float* __restrict__ zm_w, const float* __restrict__ zm_b,
    const float* __restrict__ zv_w, const float* __restrict__ zv_b,
    const float* __restrict__ g1w, const float* __restrict__ g2w,
    float* __restrict__ out)
{
    if (blockIdx.x >= 32) {
        int idx = (blockIdx.x - 32) * 320 + threadIdx.x;   // [0, 102400)
        {
            int r = idx / 320, c = idx - r * 320;
            float v = (r < NH && c < NH) ? g2w[r * NH + c] : 0.f;
            g_g2hi[idx] = __float2half_rn(v);
        }
        if (idx < 320 * 64) {
            int r = idx >> 6, c = idx & 63;
            float v = (r < NH) ? g1w[r * NL + c] : 0.f;
            __half h, l; split_f16(v, h, l);
            g_g1hi[idx] = h; g_g1lo[idx] = l;
        }
        return;
    }

    __shared__ float xs[8][ND];       // 16 KB
    __shared__ float h1s[8][NH];
    __shared__ float h2s[8][NH];

    const int b0 = blockIdx.x * 8;
    const int t = threadIdx.x;

    for (int idx = t; idx < 8 * ND; idx += 320)
        xs[idx >> 9][idx & 511] = x[b0 * ND + idx];
    __syncthreads();

    if (t < NH) {
        float acc[8];
        float bb = enc1_b[t];
        #pragma unroll
        for (int r = 0; r < 8; r++) acc[r] = bb;
        const float4* w4 = reinterpret_cast<const float4*>(enc1_w + t * ND);
        #pragma unroll 2
        for (int k = 0; k < ND / 4; k++) {
            float4 w = w4[k];
            #pragma unroll
            for (int r = 0; r < 8; r++) {
                float4 xv = reinterpret_cast<const float4*>(xs[r])[k];   // broadcast
                acc[r] += w.x * xv.x + w.y * xv.y + w.z * xv.z + w.w * xv.w;
            }
        }
        #pragma unroll
        for (int r = 0; r < 8; r++) h1s[r][t] = fmaxf(acc[r], 0.f);
    }
    __syncthreads();

    if (t < NH) {
        float acc[8];
        float bb = enc2_b[t];
        #pragma unroll
        for (int r = 0; r < 8; r++) acc[r] = bb;
        const float4* w4 = reinterpret_cast<const float4*>(enc2_w + t * NH);
        #pragma unroll 2
        for (int k = 0; k < NH / 4; k++) {
            float4 w = w4[k];
            #pragma unroll
            for (int r = 0; r < 8; r++) {
                float4 hv = reinterpret_cast<const float4*>(h1s[r])[k];  // broadcast
                acc[r] += w.x * hv.x + w.y * hv.y + w.z * hv.z + w.w * hv.w;
            }
        }
        #pragma unroll
        for (int r = 0; r < 8; r++) h2s[r][t] = fmaxf(acc[r], 0.f);
    }
    __syncthreads();

    if (t < NL) {
        float am[8], av[8];
        float bm = zm_b[t], bv = zv_b[t];
        #pragma unroll
        for (int r = 0; r < 8; r++) { am[r] = bm; av[r] = bv; }
        const float4* wm4 = reinterpret_cast<const float4*>(zm_w + t * NH);
        const float4* wv4 = reinterpret_cast<const float4*>(zv_w + t * NH);
        #pragma unroll 1
        for (int k = 0; k < NH / 4; k++) {
            float4 wm = wm4[k];
            float4 wv = wv4[k];
            #pragma unroll
            for (int r = 0; r < 8; r++) {
                float4 hv = reinterpret_cast<const float4*>(h2s[r])[k];  // broadcast
                am[r] += wm.x * hv.x + wm.y * hv.y + wm.z * hv.z + wm.w * hv.w;
                av[r] += wv.x * hv.x + wv.y * hv.y + wv.z * hv.z + wv.w * hv.w;
            }
        }
        float* oz = out + NB * ND;
        #pragma unroll
        for (int r = 0; r < 8; r++) {
            int b = b0 + r;
            float e = eps[b * NL + t];
            float z = am[r] + e * expf(0.5f * av[r]);
            g_zT[t * NB + b] = z;
            oz[b * NL + t] = z;
            oz[NB * NL + b * NL + t] = am[r];
            oz[2 * NB * NL + b * NL + t] = av[r];
        }
    }
}

// ---------------------------------------------------------------------------
// Decoder: one CTA = (one column d, 64 batch rows). 256 threads, 8 warps,
// 2 CTAs/SM. Unified 12-piece cp.async pipeline:
//   pieces 0-3:  gen1 B (80 rows hi+lo)  -> GEMM1 fp16 3-term, g1 -> SMEM (hi)
//   pieces 4-11: gen2 B hi (40 cols)     -> GEMM2 fp16 1-term + fused epilogue
// ---------------------------------------------------------------------------
__global__ __launch_bounds__(256, 2) void decoder_kernel(
    const float* __restrict__ Wmat, const float* __restrict__ gen2_b,
    const float* __restrict__ head_w, const float* __restrict__ head_b,
    float* __restrict__ out_x)
{
    extern __shared__ char sm[];
    const uint32_t sb = smem_u32(sm);
    const int tid = threadIdx.x, warp = tid >> 5, lane = tid & 31;
    const int mw = warp & 3, nh = warp >> 2;
    const int d = blockIdx.x, b0 = blockIdx.y * CM;

    float* head_s = (float*)(sm + OFF_HEAD);
    float* bias_s = (float*)(sm + OFF_BIAS);

    // ---- issue gen1 B pieces 0,1 ------------------------------------------
    #pragma unroll
    for (int p0 = 0; p0 < 2; p0++) {
        const char* srch = (const char*)(g_g1hi + p0 * 80 * 64);
        const char* srcl = (const char*)(g_g1lo + p0 * 80 * 64);
        uint32_t bufb = sb + OFF_B + p0 * BUFSZ;
        for (int idx = tid; idx < 640; idx += 256) {
            uint32_t doff = (uint32_t)((idx >> 3) * STR1 + (idx & 7) * 16);
            cp16(bufb + doff, srch + idx * 16);
            cp16(bufb + B1LO_OFF + doff, srcl + idx * 16);
        }
        cp_commit();
    }

    // ---- head/bias + masked split while loads fly --------------------------
    for (int i = tid; i < 320; i += 256) {
        head_s[i] = (i < NH) ? head_w[d * NH + i] : 0.f;
        bias_s[i] = (i < NH) ? gen2_b[i] : 0.f;
    }
    for (int idx = tid; idx < CM * NL; idx += 256) {
        int m = idx & 63, l = idx >> 6;
        float v = g_zT[l * NB + b0 + m] * Wmat[d * NL + l];
        __half h, lo; split_f16(v, h, lo);
        *(__half*)(sm + OFF_MHI + m * STR1 + l * 2) = h;
        *(__half*)(sm + OFF_MLO + m * STR1 + l * 2) = lo;
    }

    const uint32_t a1base = sb + OFF_MHI + (mw * 16 + (lane & 15)) * STR1 + ((lane >> 4) & 1) * 16;
    const uint32_t a2base = sb + OFF_G1  + (mw * 16 + (lane & 15)) * STR2 + ((lane >> 4) & 1) * 16;

    // ---- GEMM1: 4 pieces of 80 h-cols (fp16 3-term) ------------------------
    #pragma unroll 1
    for (int i = 0; i < 4; i++) {
        cp_wait1();
        __syncthreads();
        const uint32_t bufb = sb + OFF_B + (uint32_t)((i & 1) * BUFSZ);

        float acc[5][4];
        #pragma unroll
        for (int t = 0; t < 5; t++) { acc[t][0] = acc[t][1] = acc[t][2] = acc[t][3] = 0.f; }
        #pragma unroll
        for (int ks = 0; ks < 4; ks++) {
            uint32_t ahi[4], alo[4], bhi[2], blo[2];
            ldsm_x4(ahi, a1base + ks * 32);
            ldsm_x4(alo, a1base + (OFF_MLO - OFF_MHI) + ks * 32);
            #pragma unroll
            for (int t = 0; t < 5; t++) {
                uint32_t bb = bufb + (nh * 40 + t * 8 + (lane & 7)) * STR1
                            + ((lane >> 3) & 1) * 16 + ks * 32;
                ldsm_x2(bhi, bb);
                ldsm_x2(blo, bb + B1LO_OFF);
                mma_f16(acc[t], ahi, bhi);
                mma_f16(acc[t], alo, bhi);
                mma_f16(acc[t], ahi, blo);
            }
        }
        // ReLU + fp16 store of g1 (hi only)
        #pragma unroll
        for (int t = 0; t < 5; t++) {
            int col = i * 80 + nh * 40 + t * 8 + 2 * (lane & 3);
            if (col < 304) {
                int r0 = mw * 16 + (lane >> 2);
                *(uint32_t*)(sm + OFF_G1 + r0 * STR2 + col * 2) =
                    pack_relu2(acc[t][0], acc[t][1]);
                *(uint32_t*)(sm + OFF_G1 + (r0 + 8) * STR2 + col * 2) =
                    pack_relu2(acc[t][2], acc[t][3]);
            }
        }
        __syncthreads();   // buf[i&1] fully consumed

        // prefetch piece i+2: gen1 pieces 2,3 then gen2 pieces 0,1
        if (i + 2 < 4) {
            const int pn = i + 2;
            const char* srch = (const char*)(g_g1hi + pn * 80 * 64);
            const char* srcl = (const char*)(g_g1lo + pn * 80 * 64);
            for (int idx = tid; idx < 640; idx += 256) {
                uint32_t doff = (uint32_t)((idx >> 3) * STR1 + (idx & 7) * 16);
                cp16(bufb + doff, srch + idx * 16);
                cp16(bufb + B1LO_OFF + doff, srcl + idx * 16);
            }
        } else {
            const int j = i - 2;   // gen2 piece 0 or 1
            for (int idx = tid; idx < 40 * 38; idx += 256) {
                int r = idx / 38, q = idx - r * 38;
                cp16(bufb + r * STR2 + q * 16,
                     (const char*)(g_g2hi + (j * 40 + r) * 320) + q * 16);
            }
        }
        cp_commit();
    }

    // ---- GEMM2: 8 pieces of 40 g-cols (fp16 1-term) + fused epilogue -------
    float xp0 = 0.f, xp1 = 0.f;
    #pragma unroll 1
    for (int j = 0; j < 8; j++) {
        if (j < 7) cp_wait1(); else cp_wait0();
        __syncthreads();
        const uint32_t bufb = sb + OFF_B + (uint32_t)((j & 1) * BUFSZ);

        // alternate 3/2 tile split between nh groups for balance
        const int n0 = (j & 1) ? 2 : 3;          // tiles for nh=0
        const int tstart = nh ? n0 : 0;
        const int tcnt = nh ? (5 - n0) : n0;

        float acc[3][4];
        #pragma unroll
        for (int t = 0; t < 3; t++) { acc[t][0] = acc[t][1] = acc[t][2] = acc[t][3] = 0.f; }
        #pragma unroll 1
        for (int ks = 0; ks < 19; ks++) {
            uint32_t ahi[4], b[2];
            ldsm_x4(ahi, a2base + ks * 32);
            #pragma unroll
            for (int t = 0; t < 3; t++) {
                if (t < tcnt) {
                    ldsm_x2(b, bufb + ((tstart + t) * 8 + (lane & 7)) * STR2
                              + ((lane >> 3) & 1) * 16 + ks * 32);
                    mma_f16(acc[t], ahi, b);
                }
            }
        }
        // fused epilogue
        #pragma unroll
        for (int t = 0; t < 3; t++) {
            if (t < tcnt) {
                int g = j * 40 + (tstart + t) * 8 + 2 * (lane & 3);
                float bb0 = bias_s[g], bb1 = bias_s[g + 1];
                float hh0 = head_s[g], hh1 = head_s[g + 1];
                xp0 = fmaf(fmaxf(acc[t][0] + bb0, 0.f), hh0, xp0);
                xp0 = fmaf(fmaxf(acc[t][1] + bb1, 0.f), hh1, xp0);
                xp1 = fmaf(fmaxf(acc[t][2] + bb0, 0.f), hh0, xp1);
                xp1 = fmaf(fmaxf(acc[t][3] + bb1, 0.f), hh1, xp1);
            }
        }

        if (j + 2 < 8) {
            __syncthreads();   // buf[j&1] fully consumed
            const int pn = j + 2;
            for (int idx = tid; idx < 40 * 38; idx += 256) {
                int r = idx / 38, q = idx - r * 38;
                cp16(bufb + r * STR2 + q * 16,
                     (const char*)(g_g2hi + (pn * 40 + r) * 320) + q * 16);
            }
            cp_commit();
        }
    }

    // quad reduce (over the 4 col-groups)
    xp0 += __shfl_xor_sync(0xFFFFFFFFu, xp0, 1);
    xp0 += __shfl_xor_sync(0xFFFFFFFFu, xp0, 2);
    xp1 += __shfl_xor_sync(0xFFFFFFFFu, xp1, 1);
    xp1 += __shfl_xor_sync(0xFFFFFFFFu, xp1, 2);

    float* xr = (float*)(sm + OFF_XRED);   // [2 nh][64 rows]
    __syncthreads();
    if ((lane & 3) == 0) {
        int r0 = mw * 16 + (lane >> 2);
        xr[nh * 64 + r0] = xp0;
        xr[nh * 64 + r0 + 8] = xp1;
    }
    __syncthreads();
    if (tid < CM)
        out_x[(b0 + tid) * ND + d] = xr[tid] + xr[64 + tid] + head_b[d];
}

extern "C" void kernel_launch(void* const* d_in, const int* in_sizes, int n_in,
                              void* d_out, int out_size)
{
    const float* x      = (const float*)d_in[0];
    const float* eps    = (const float*)d_in[1];
    const float* Wmat   = (const float*)d_in[2];
    const float* enc1_w = (const float*)d_in[3];
    const float* enc1_b = (const float*)d_in[4];
    const float* enc2_w = (const float*)d_in[5];
    const float* enc2_b = (const float*)d_in[6];
    const float* zm_w   = (const float*)d_in[7];
    const float* zm_b   = (const float*)d_in[8];
    const float* zv_w   = (const float*)d_in[9];
    const float* zv_b   = (const float*)d_in[10];
    const float* gen1_w = (const float*)d_in[11];
    const float* gen2_w = (const float*)d_in[12];
    const float* gen2_b = (const float*)d_in[13];
    const float* head_w = (const float*)d_in[14];
    const float* head_b = (const float*)d_in[15];
    float* out = (float*)d_out;

    static bool attr_set = false;
    if (!attr_set) {
        cudaFuncSetAttribute(decoder_kernel,
                             cudaFuncAttributeMaxDynamicSharedMemorySize, SMEM_TOTAL);
        attr_set = true;
    }

    pre_kernel<<<352, 320>>>(x, eps, enc1_w, enc1_b, enc2_w, enc2_b,
                             zm_w, zm_b, zv_w, zv_b, gen1_w, gen2_w, out);
    decoder_kernel<<<dim3(ND, NB / CM), 256, SMEM_TOTAL>>>(
        Wmat, gen2_b, head_w, head_b, out);
}

// round 15
// speedup vs baseline: 10.6731x; 1.3134x over previous
#include <cuda_runtime.h>
#include <cuda_fp16.h>
#include <cstdint>

#define NB 256
#define ND 512
#define NL 64
#define NH 300
#define CM 64                 // batch rows per decoder CTA

// strides (bytes) for k-major SMEM operands
#define STR1 144              // k=64 padded to 72 halves
#define STR2 624              // k=304 padded to 312 halves

// ---- decoder SMEM layout (bytes) ------------------------------------------
#define OFF_G1    0                        // g1 fp16 [64][312h] = 39936
#define OFF_MHI   39936                    // masked hi 64*144 = 9216 (XCH later)
#define OFF_MLO   49152                    // masked lo 9216
#define OFF_XCH   OFF_MHI                  // split-k exchange (10240 B, GEMM2 only)
#define OFF_B     58368                    // two ping-pong buffers
#define BUFSZ     24960                    // B1 piece 11520 / B2 piece 24960
#define OFF_HEAD  108288                   // 320 floats
#define OFF_BIAS  109568                   // 320 floats
#define OFF_XRED  110848                   // 64 floats
#define SMEM_TOTAL 111360

__device__ __align__(16) float g_zT[NL * NB];       // z transposed [l][b]
__device__ __align__(16) __half g_g1hi[320 * 64];   // gen1 hi, padded rows
__device__ __align__(16) __half g_g2hi[320 * 320];  // gen2 hi only

// ---------------- helpers --------------------------------------------------
static __device__ __forceinline__ uint32_t smem_u32(const void* p) {
    uint32_t a;
    asm("{ .reg .u64 t; cvta.to.shared.u64 t, %1; cvt.u32.u64 %0, t; }" : "=r"(a) : "l"(p));
    return a;
}
static __device__ __forceinline__ void ldsm_x4(uint32_t* r, uint32_t addr) {
    asm volatile("ldmatrix.sync.aligned.m8n8.x4.shared.b16 {%0,%1,%2,%3}, [%4];"
                 : "=r"(r[0]), "=r"(r[1]), "=r"(r[2]), "=r"(r[3]) : "r"(addr));
}
static __device__ __forceinline__ void ldsm_x2(uint32_t* r, uint32_t addr) {
    asm volatile("ldmatrix.sync.aligned.m8n8.x2.shared.b16 {%0,%1}, [%2];"
                 : "=r"(r[0]), "=r"(r[1]) : "r"(addr));
}
static __device__ __forceinline__ void mma_f16(float* c, const uint32_t* a, const uint32_t* b) {
    asm volatile("mma.sync.aligned.m16n8k16.row.col.f32.f16.f16.f32 "
                 "{%0,%1,%2,%3}, {%4,%5,%6,%7}, {%8,%9}, {%0,%1,%2,%3};"
                 : "+f"(c[0]), "+f"(c[1]), "+f"(c[2]), "+f"(c[3])
                 : "r"(a[0]), "r"(a[1]), "r"(a[2]), "r"(a[3]), "r"(b[0]), "r"(b[1]));
}
static __device__ __forceinline__ void cp16(uint32_t dst, const void* src) {
    asm volatile("cp.async.cg.shared.global [%0], [%1], 16;" :: "r"(dst), "l"(src) : "memory");
}
static __device__ __forceinline__ void cp_commit() { asm volatile("cp.async.commit_group;" ::: "memory"); }
static __device__ __forceinline__ void cp_wait0()  { asm volatile("cp.async.wait_group 0;" ::: "memory"); }
static __device__ __forceinline__ void cp_wait1()  { asm volatile("cp.async.wait_group 1;" ::: "memory"); }

static __device__ __forceinline__ void split_f16(float v, __half& h, __half& l) {
    h = __float2half_rn(v);
    l = __float2half_rn(v - __half2float(h));
}
static __device__ __forceinline__ uint32_t pack_relu2(float v0, float v1) {
    __half h0 = __float2half_rn(fmaxf(v0, 0.f));
    __half h1 = __float2half_rn(fmaxf(v1, 0.f));
    return (uint32_t)__half_as_ushort(h0) | ((uint32_t)__half_as_ushort(h1) << 16);
}

// ---------------------------------------------------------------------------
// Pre: blocks [0, 64) = encoder (4 batch rows per CTA);
//      blocks [64, 384) = weight prep (gen1 hi padded, gen2 hi).
// ---------------------------------------------------------------------------
__global__ __launch_bounds__(320) void pre_kernel(
    const float* __restrict__ x, const float* __restrict__ eps,
    const float* __restrict__ enc1_w, const float* __restrict__ enc1_b,
    const float* __restrict__ enc2_w, const float* __restrict__ enc2_b,
    const float* __restrict__ zm_w, const float* __restrict__ zm_b,
    const float* __restrict__ zv_w, const float* __restrict__ zv_b,
    const float* __restrict__ g1w, const float* __restrict__ g2w,
    float* __restrict__ out)
{
    const int t = threadIdx.x;
    if (blockIdx.x >= 64) {
        int idx = (blockIdx.x - 64) * 320 + t;   // [0, 102400)
        {
            int r = idx / 320, c = idx - r * 320;
            float v = (r < NH && c < NH) ? g2w[r * NH + c] : 0.f;
            g_g2hi[idx] = __float2half_rn(v);
        }
        if (idx < 320 * 64) {
            int r = idx >> 6, c = idx & 63;
            float v = (r < NH) ? g1w[r * NL + c] : 0.f;
            g_g1hi[idx] = __float2half_rn(v);
        }
        return;
    }

    __shared__ float xs[4][ND];
    __shared__ float h1s[4][NH];
    __shared__ float h2s[4][NH];
    __shared__ float zms[4][NL];
    __shared__ float zvs[4][NL];

    const int b0 = blockIdx.x * 4;

    for (int idx = t; idx < 4 * ND; idx += 320)
        xs[idx >> 9][idx & 511] = x[b0 * ND + idx];
    __syncthreads();

    if (t < NH) {
        float acc[4];
        float bb = enc1_b[t];
        #pragma unroll
        for (int r = 0; r < 4; r++) acc[r] = bb;
        const float4* w4 = reinterpret_cast<const float4*>(enc1_w + t * ND);
        #pragma unroll 2
        for (int k = 0; k < ND / 4; k++) {
            float4 w = w4[k];
            #pragma unroll
            for (int r = 0; r < 4; r++) {
                float4 xv = reinterpret_cast<const float4*>(xs[r])[k];
                acc[r] += w.x * xv.x + w.y * xv.y + w.z * xv.z + w.w * xv.w;
            }
        }
        #pragma unroll
        for (int r = 0; r < 4; r++) h1s[r][t] = fmaxf(acc[r], 0.f);
    }
    __syncthreads();

    if (t < NH) {
        float acc[4];
        float bb = enc2_b[t];
        #pragma unroll
        for (int r = 0; r < 4; r++) acc[r] = bb;
        const float4* w4 = reinterpret_cast<const float4*>(enc2_w + t * NH);
        #pragma unroll 2
        for (int k = 0; k < NH / 4; k++) {
            float4 w = w4[k];
            #pragma unroll
            for (int r = 0; r < 4; r++) {
                float4 hv = reinterpret_cast<const float4*>(h1s[r])[k];
                acc[r] += w.x * hv.x + w.y * hv.y + w.z * hv.z + w.w * hv.w;
            }
        }
        #pragma unroll
        for (int r = 0; r < 4; r++) h2s[r][t] = fmaxf(acc[r], 0.f);
    }
    __syncthreads();

    float* oz = out + NB * ND;
    if (t < 128) {
        const int half = t >> 6, l = t & 63;
        const float* wbase = half ? zv_w : zm_w;
        float bb = half ? zv_b[l] : zm_b[l];
        float ac[4];
        #pragma unroll
        for (int r = 0; r < 4; r++) ac[r] = bb;
        const float4* w4 = reinterpret_cast<const float4*>(wbase + l * NH);
        #pragma unroll 1
        for (int k = 0; k < NH / 4; k++) {
            float4 w = w4[k];
            #pragma unroll
            for (int r = 0; r < 4; r++) {
                float4 hv = reinterpret_cast<const float4*>(h2s[r])[k];
                ac[r] += w.x * hv.x + w.y * hv.y + w.z * hv.z + w.w * hv.w;
            }
        }
        #pragma unroll
        for (int r = 0; r < 4; r++) {
            int b = b0 + r;
            if (half) { zvs[r][l] = ac[r]; oz[2 * NB * NL + b * NL + l] = ac[r]; }
            else      { zms[r][l] = ac[r]; oz[NB * NL + b * NL + l] = ac[r]; }
        }
    }
    __syncthreads();
    if (t < 64) {
        #pragma unroll
        for (int r = 0; r < 4; r++) {
            int b = b0 + r;
            float e = eps[b * NL + t];
            float z = zms[r][t] + e * expf(0.5f * zvs[r][t]);
            g_zT[t * NB + b] = z;
            oz[b * NL + t] = z;
        }
    }
}

// ---------------------------------------------------------------------------
// Decoder: one CTA = (one column d, 64 batch rows). 256 threads, 8 warps,
// 2 CTAs/SM. mw = warp&3 (16-row m-block), nh = warp>>2.
// GEMM1 (fp16 2-term: Ahi*B + Alo*B), gen1-hi B streamed in 4 pieces of 80
//   h-cols (nh splits cols 40/40), paired ldsm_x4 B loads.
// GEMM2 (fp16 1-term) split-k: nh=0 holds ks 0-9 in regs, nh=1 ks 10-18;
//   gen2-hi B streamed in 8 pieces of 40 g-cols; partial sums exchanged via
//   SMEM before fused bias+ReLU+head epilogue (nh=0).
// ---------------------------------------------------------------------------
__global__ __launch_bounds__(256, 2) void decoder_kernel(
    const float* __restrict__ Wmat, const float* __restrict__ gen2_b,
    const float* __restrict__ head_w, const float* __restrict__ head_b,
    float* __restrict__ out_x)
{
    extern __shared__ char sm[];
    const uint32_t sb = smem_u32(sm);
    const int tid = threadIdx.x, warp = tid >> 5, lane = tid & 31;
    const int mw = warp & 3, nh = warp >> 2;
    const int d = blockIdx.x, b0 = blockIdx.y * CM;

    float* head_s = (float*)(sm + OFF_HEAD);
    float* bias_s = (float*)(sm + OFF_BIAS);

    // ---- issue gen1 B pieces 0,1 (hi only: 80 rows x 128B) -----------------
    #pragma unroll
    for (int p0 = 0; p0 < 2; p0++) {
        const char* src = (const char*)(g_g1hi + p0 * 80 * 64);
        uint32_t bufb = sb + OFF_B + p0 * BUFSZ;
        for (int idx = tid; idx < 640; idx += 256) {
            uint32_t doff = (uint32_t)((idx >> 3) * STR1 + (idx & 7) * 16);
            cp16(bufb + doff, src + idx * 16);
        }
        cp_commit();
    }

    // ---- head/bias + masked split while loads fly --------------------------
    for (int i = tid; i < 320; i += 256) {
        head_s[i] = (i < NH) ? head_w[d * NH + i] : 0.f;
        bias_s[i] = (i < NH) ? gen2_b[i] : 0.f;
    }
    for (int idx = tid; idx < CM * NL; idx += 256) {
        int m = idx & 63, l = idx >> 6;
        float v = g_zT[l * NB + b0 + m] * Wmat[d * NL + l];
        __half h, lo; split_f16(v, h, lo);
        *(__half*)(sm + OFF_MHI + m * STR1 + l * 2) = h;
        *(__half*)(sm + OFF_MLO + m * STR1 + l * 2) = lo;
    }

    const uint32_t a1base = sb + OFF_MHI + (mw * 16 + (lane & 15)) * STR1 + ((lane >> 4) & 1) * 16;
    const uint32_t a2base = sb + OFF_G1  + (mw * 16 + (lane & 15)) * STR2 + ((lane >> 4) & 1) * 16;

    // ---- GEMM1: 4 pieces of 80 h-cols (2-term, paired B loads) -------------
    #pragma unroll 1
    for (int i = 0; i < 4; i++) {
        cp_wait1();
        __syncthreads();
        const uint32_t bufb = sb + OFF_B + (uint32_t)((i & 1) * BUFSZ);

        float acc[5][4];
        #pragma unroll
        for (int t = 0; t < 5; t++) { acc[t][0] = acc[t][1] = acc[t][2] = acc[t][3] = 0.f; }
        #pragma unroll
        for (int ks = 0; ks < 4; ks++) {
            uint32_t ahi[4], alo[4], b4[4], b2[2];
            ldsm_x4(ahi, a1base + ks * 32);
            ldsm_x4(alo, a1base + (OFF_MLO - OFF_MHI) + ks * 32);
            #pragma unroll
            for (int tp = 0; tp < 2; tp++) {
                uint32_t bb = bufb + (uint32_t)((nh * 40 + tp * 16 + ((lane >> 4) & 1) * 8 + (lane & 7)) * STR1)
                            + ((lane >> 3) & 1) * 16 + ks * 32;
                ldsm_x4(b4, bb);
                mma_f16(acc[2 * tp],     ahi, b4);     mma_f16(acc[2 * tp],     alo, b4);
                mma_f16(acc[2 * tp + 1], ahi, b4 + 2); mma_f16(acc[2 * tp + 1], alo, b4 + 2);
            }
            uint32_t bb2 = bufb + (uint32_t)((nh * 40 + 32 + (lane & 7)) * STR1)
                         + ((lane >> 3) & 1) * 16 + ks * 32;
            ldsm_x2(b2, bb2);
            mma_f16(acc[4], ahi, b2); mma_f16(acc[4], alo, b2);
        }
        // ReLU + fp16 store of g1
        #pragma unroll
        for (int t = 0; t < 5; t++) {
            int col = i * 80 + nh * 40 + t * 8 + 2 * (lane & 3);
            if (col < 304) {
                int r0 = mw * 16 + (lane >> 2);
                *(uint32_t*)(sm + OFF_G1 + r0 * STR2 + col * 2) = pack_relu2(acc[t][0], acc[t][1]);
                *(uint32_t*)(sm + OFF_G1 + (r0 + 8) * STR2 + col * 2) = pack_relu2(acc[t][2], acc[t][3]);
            }
        }
        __syncthreads();   // buf consumed + g1 piece visible

        // prefetch piece i+2: gen1 pieces 2,3 then gen2 pieces 0,1
        if (i + 2 < 4) {
            const char* src = (const char*)(g_g1hi + (i + 2) * 80 * 64);
            for (int idx = tid; idx < 640; idx += 256) {
                uint32_t doff = (uint32_t)((idx >> 3) * STR1 + (idx & 7) * 16);
                cp16(bufb + doff, src + idx * 16);
            }
        } else {
            const int j = i - 2;
            for (int idx = tid; idx < 40 * 38; idx += 256) {
                int r = idx / 38, q = idx - r * 38;
                cp16(bufb + r * STR2 + q * 16,
                     (const char*)(g_g2hi + (j * 40 + r) * 320) + q * 16);
            }
        }
        cp_commit();
    }

    // ---- load A2 (g1) fragments into registers: nh-split of ks -------------
    const int ksbase = nh * 10;
    uint32_t a2r[10][4];
    #pragma unroll
    for (int k = 0; k < 10; k++)
        if (ksbase + k < 19) ldsm_x4(a2r[k], a2base + (ksbase + k) * 32);

    // ---- GEMM2: 8 pieces of 40 g-cols (1-term, A in regs, split-k) ---------
    float xp0 = 0.f, xp1 = 0.f;
    #pragma unroll 1
    for (int j = 0; j < 8; j++) {
        if (j < 7) cp_wait1(); else cp_wait0();
        __syncthreads();
        const uint32_t bufb = sb + OFF_B + (uint32_t)((j & 1) * BUFSZ);

        float acc[5][4];
        #pragma unroll
        for (int t = 0; t < 5; t++) { acc[t][0] = acc[t][1] = acc[t][2] = acc[t][3] = 0.f; }
        #pragma unroll
        for (int k = 0; k < 10; k++) {
            if (ksbase + k < 19) {
                uint32_t b4[4], b2[2];
                #pragma unroll
                for (int tp = 0; tp < 2; tp++) {
                    uint32_t bb = bufb + (uint32_t)((tp * 16 + ((lane >> 4) & 1) * 8 + (lane & 7)) * STR2)
                                + ((lane >> 3) & 1) * 16 + (ksbase + k) * 32;
                    ldsm_x4(b4, bb);
                    mma_f16(acc[2 * tp],     a2r[k], b4);
                    mma_f16(acc[2 * tp + 1], a2r[k], b4 + 2);
                }
                uint32_t bb2 = bufb + (uint32_t)((32 + (lane & 7)) * STR2)
                             + ((lane >> 3) & 1) * 16 + (ksbase + k) * 32;
                ldsm_x2(b2, bb2);
                mma_f16(acc[4], a2r[k], b2);
            }
        }

        // split-k exchange: nh=1 posts partials; sync also frees B buffer
        if (nh == 1) {
            #pragma unroll
            for (int t = 0; t < 5; t++) {
                float4 v = make_float4(acc[t][0], acc[t][1], acc[t][2], acc[t][3]);
                *(float4*)(sm + OFF_XCH + (((mw * 32 + lane) * 5 + t) << 4)) = v;
            }
        }
        __syncthreads();

        if (nh == 0) {
            #pragma unroll
            for (int t = 0; t < 5; t++) {
                float4 p = *(const float4*)(sm + OFF_XCH + (((mw * 32 + lane) * 5 + t) << 4));
                float s0 = acc[t][0] + p.x, s1 = acc[t][1] + p.y;
                float s2 = acc[t][2] + p.z, s3 = acc[t][3] + p.w;
                int g = j * 40 + t * 8 + 2 * (lane & 3);
                float bb0 = bias_s[g], bb1 = bias_s[g + 1];
                float hh0 = head_s[g], hh1 = head_s[g + 1];
                xp0 = fmaf(fmaxf(s0 + bb0, 0.f), hh0, xp0);
                xp0 = fmaf(fmaxf(s1 + bb1, 0.f), hh1, xp0);
                xp1 = fmaf(fmaxf(s2 + bb0, 0.f), hh0, xp1);
                xp1 = fmaf(fmaxf(s3 + bb1, 0.f), hh1, xp1);
            }
        }

        if (j + 2 < 8) {
            for (int idx = tid; idx < 40 * 38; idx += 256) {
                int r = idx / 38, q = idx - r * 38;
                cp16(bufb + r * STR2 + q * 16,
                     (const char*)(g_g2hi + ((j + 2) * 40 + r) * 320) + q * 16);
            }
            cp_commit();
        }
    }

    // final reduce on nh=0 warps (quad reduce over 4 col-groups)
    float* xr = (float*)(sm + OFF_XRED);   // 64 rows
    if (nh == 0) {
        xp0 += __shfl_xor_sync(0xFFFFFFFFu, xp0, 1);
        xp0 += __shfl_xor_sync(0xFFFFFFFFu, xp0, 2);
        xp1 += __shfl_xor_sync(0xFFFFFFFFu, xp1, 1);
        xp1 += __shfl_xor_sync(0xFFFFFFFFu, xp1, 2);
    }
    __syncthreads();
    if (nh == 0 && (lane & 3) == 0) {
        int r0 = mw * 16 + (lane >> 2);
        xr[r0] = xp0;
        xr[r0 + 8] = xp1;
    }
    __syncthreads();
    if (tid < CM)
        out_x[(b0 + tid) * ND + d] = xr[tid] + head_b[d];
}

extern "C" void kernel_launch(void* const* d_in, const int* in_sizes, int n_in,
                              void* d_out, int out_size)
{
    const float* x      = (const float*)d_in[0];
    const float* eps    = (const float*)d_in[1];
    const float* Wmat   = (const float*)d_in[2];
    const float* enc1_w = (const float*)d_in[3];
    const float* enc1_b = (const float*)d_in[4];
    const float* enc2_w = (const float*)d_in[5];
    const float* enc2_b = (const float*)d_in[6];
    const float* zm_w   = (const float*)d_in[7];
    const float* zm_b   = (const float*)d_in[8];
    const float* zv_w   = (const float*)d_in[9];
    const float* zv_b   = (const float*)d_in[10];
    const float* gen1_w = (const float*)d_in[11];
    const float* gen2_w = (const float*)d_in[12];
    const float* gen2_b = (const float*)d_in[13];
    const float* head_w = (const float*)d_in[14];
    const float* head_b = (const float*)d_in[15];
    float* out = (float*)d_out;

    static bool attr_set = false;
    if (!attr_set) {
        cudaFuncSetAttribute(decoder_kernel,
                             cudaFuncAttributeMaxDynamicSharedMemorySize, SMEM_TOTAL);
        attr_set = true;
    }

    pre_kernel<<<384, 320>>>(x, eps, enc1_w, enc1_b, enc2_w, enc2_b,
                             zm_w, zm_b, zv_w, zv_b, gen1_w, gen2_w, out);
    decoder_kernel<<<dim3(ND, NB / CM), 256, SMEM_TOTAL>>>(
        Wmat, gen2_b, head_w, head_b, out);
}